// round 13
// baseline (speedup 1.0000x reference)
#include <cuda_runtime.h>
#include <cuda_fp16.h>
#include <math.h>
#include <stdint.h>

#define B_ 4
#define N_ 2048
#define C_ 1024
#define H_ 16
#define D_ 64
#define FF_ 4096
#define M_ (B_ * N_)   // 8192 rows

// ---------------- scratch ----------------------------------------------------
__device__ float  g_x1 [M_ * C_];      // residual after attention (fp32)
__device__ __half g_hh [M_ * C_];      // LN output (half)
__device__ __half g_qkvh[M_ * 3 * C_]; // qkv projections (half)
__device__ __half g_oh [M_ * C_];      // attention output (half)
__device__ __half g_ah [M_ * FF_];     // h@w1^T  -> silu(a)*b (half)
__device__ __half g_bh [M_ * FF_];     // h@w3^T (half)
// fp16 weights
__device__ __half g_wqh[3 * C_ * C_];
__device__ __half g_wph[C_ * C_];
__device__ __half g_w1h[FF_ * C_];
__device__ __half g_w2h[C_ * FF_];
__device__ __half g_w3h[FF_ * C_];

// ---------------- helpers ----------------------------------------------------
__device__ __forceinline__ uint32_t smem_u32(const void* p) {
    uint32_t a;
    asm("{ .reg .u64 t; cvta.to.shared.u64 t, %1; cvt.u32.u64 %0, t; }" : "=r"(a) : "l"(p));
    return a;
}
__device__ __forceinline__ uint32_t h2_u32(__half2 h) {
    return *reinterpret_cast<uint32_t*>(&h);
}
__device__ __forceinline__ __half2 u32_h2(uint32_t u) {
    return *reinterpret_cast<__half2*>(&u);
}
#define CP_ASYNC16(dst, src) \
    asm volatile("cp.async.cg.shared.global [%0], [%1], 16;" :: "r"(dst), "l"(src))
#define CP_COMMIT() asm volatile("cp.async.commit_group;" ::: "memory")
#define CP_WAIT(n)  asm volatile("cp.async.wait_group %0;" :: "n"(n) : "memory")

#define LDM_X4(r0, r1, r2, r3, addr) \
    asm volatile("ldmatrix.sync.aligned.m8n8.x4.shared.b16 {%0,%1,%2,%3}, [%4];" \
                 : "=r"(r0), "=r"(r1), "=r"(r2), "=r"(r3) : "r"(addr))
#define LDM_X4_T(r0, r1, r2, r3, addr) \
    asm volatile("ldmatrix.sync.aligned.m8n8.x4.trans.shared.b16 {%0,%1,%2,%3}, [%4];" \
                 : "=r"(r0), "=r"(r1), "=r"(r2), "=r"(r3) : "r"(addr))

__device__ __forceinline__ void mma_f16(float* c, const uint32_t* a,
                                        uint32_t b0, uint32_t b1) {
    asm volatile(
        "mma.sync.aligned.m16n8k16.row.col.f32.f16.f16.f32 "
        "{%0,%1,%2,%3}, {%4,%5,%6,%7}, {%8,%9}, {%0,%1,%2,%3};"
        : "+f"(c[0]), "+f"(c[1]), "+f"(c[2]), "+f"(c[3])
        : "r"(a[0]), "r"(a[1]), "r"(a[2]), "r"(a[3]), "r"(b0), "r"(b1));
}

// ---------------- fp32 -> fp16 prepass ---------------------------------------
__global__ void __launch_bounds__(256) cvt_half_k(const float* __restrict__ in,
                                                  __half* __restrict__ out, int n4)
{
    int i = blockIdx.x * 256 + threadIdx.x;
    if (i < n4) {
        float4 v = ((const float4*)in)[i];
        __half2* o = (__half2*)out + i * 2;
        o[0] = __floats2half2_rn(v.x, v.y);
        o[1] = __floats2half2_rn(v.z, v.w);
    }
}

// ---------------- LayerNorm (half output) ------------------------------------
__global__ void __launch_bounds__(256) layernorm_k(
    const float* __restrict__ x, const float* __restrict__ gam,
    const float* __restrict__ bet, __half* __restrict__ out)
{
    int row = blockIdx.x;
    const float* xr = x + (size_t)row * C_;
    __half2* orow = (__half2*)(out + (size_t)row * C_);
    int t = threadIdx.x;

    float4 v = *(const float4*)(xr + t * 4);
    float s1 = v.x + v.y + v.z + v.w;
    float s2 = v.x*v.x + v.y*v.y + v.z*v.z + v.w*v.w;
    #pragma unroll
    for (int o = 16; o; o >>= 1) {
        s1 += __shfl_xor_sync(0xffffffffu, s1, o);
        s2 += __shfl_xor_sync(0xffffffffu, s2, o);
    }
    __shared__ float r1[8], r2[8];
    __shared__ float mu_s, rs_s;
    if ((t & 31) == 0) { r1[t >> 5] = s1; r2[t >> 5] = s2; }
    __syncthreads();
    if (t == 0) {
        float a = 0.f, b = 0.f;
        #pragma unroll
        for (int i = 0; i < 8; i++) { a += r1[i]; b += r2[i]; }
        float mu = a * (1.f / C_);
        float var = b * (1.f / C_) - mu * mu;
        mu_s = mu; rs_s = rsqrtf(var + 1e-6f);
    }
    __syncthreads();
    float mu = mu_s, rs = rs_s;
    float4 gv = *(const float4*)(gam + t * 4);
    float4 bv = *(const float4*)(bet + t * 4);
    float ox = (v.x - mu) * rs * gv.x + bv.x;
    float oy = (v.y - mu) * rs * gv.y + bv.y;
    float oz = (v.z - mu) * rs * gv.z + bv.z;
    float ow = (v.w - mu) * rs * gv.w + bv.w;
    orow[t * 2 + 0] = __floats2half2_rn(ox, oy);
    orow[t * 2 + 1] = __floats2half2_rn(oz, ow);
}

// ---------------- fp16 mma GEMM: C = A(MxK)*B(NxK)^T (+bias)(+res) -----------
// 128x256 tile, BK=32 halves, 4-stage cp.async, 256 threads (8 warps, 2x4),
// warp tile 64x64. 1 CTA/SM (120KB smem).
#define APITCH 80                      // bytes per smem row (64B data + 16B pad)
#define ATILE_B (128 * APITCH)         // 10240
#define BTILE_B (256 * APITCH)         // 20480
#define STAGE_B (ATILE_B + BTILE_B)    // 30720
#define HSMEM_BYTES (4 * STAGE_B)      // 122880

template<bool BIAS, bool RES, bool HOUT>
__global__ void __launch_bounds__(256, 1) hgemm(
    const __half* __restrict__ A, const __half* __restrict__ Bm,
    const float* __restrict__ bias, const float* __restrict__ res,
    void* __restrict__ Cc, int M, int Nn, int K)
{
    extern __shared__ char smc[];
    uint32_t sb = smem_u32(smc);
    const int tid = threadIdx.x;
    const int warp = tid >> 5, lane = tid & 31;
    const int m0 = blockIdx.y * 128, n0 = blockIdx.x * 256;
    const int wm = (warp >> 2) * 64, wn = (warp & 3) * 64;
    const int gr = lane >> 2, q = lane & 3;
    const int oct = lane >> 3, orow = lane & 7;

    const int lrow = tid >> 1;
    const int lc = (tid & 1) * 2;
    const __half* Ap  = A  + (size_t)(m0 + lrow) * K + lc * 8;
    const __half* Bp0 = Bm + (size_t)(n0 + lrow) * K + lc * 8;
    const __half* Bp1 = Bm + (size_t)(n0 + lrow + 128) * K + lc * 8;
    const uint32_t woA  = (uint32_t)lrow * APITCH + lc * 16;
    const uint32_t woB0 = ATILE_B + woA;
    const uint32_t woB1 = woB0 + 128 * APITCH;

    float acc[4][8][4];
    #pragma unroll
    for (int i = 0; i < 4; i++)
        #pragma unroll
        for (int j = 0; j < 8; j++)
            #pragma unroll
            for (int c = 0; c < 4; c++) acc[i][j][c] = 0.f;

    const int NS = K >> 5;

    #pragma unroll
    for (int s = 0; s < 3; s++) {
        uint32_t st = sb + (uint32_t)s * STAGE_B;
        CP_ASYNC16(st + woA,       Ap  + (size_t)s * 32);
        CP_ASYNC16(st + woA  + 16, Ap  + (size_t)s * 32 + 8);
        CP_ASYNC16(st + woB0,      Bp0 + (size_t)s * 32);
        CP_ASYNC16(st + woB0 + 16, Bp0 + (size_t)s * 32 + 8);
        CP_ASYNC16(st + woB1,      Bp1 + (size_t)s * 32);
        CP_ASYNC16(st + woB1 + 16, Bp1 + (size_t)s * 32 + 8);
        CP_COMMIT();
    }

    for (int s = 0; s < NS; s++) {
        CP_WAIT(2);
        __syncthreads();

        int ns = s + 3;
        if (ns < NS) {
            uint32_t st = sb + (uint32_t)(ns & 3) * STAGE_B;
            CP_ASYNC16(st + woA,       Ap  + (size_t)ns * 32);
            CP_ASYNC16(st + woA  + 16, Ap  + (size_t)ns * 32 + 8);
            CP_ASYNC16(st + woB0,      Bp0 + (size_t)ns * 32);
            CP_ASYNC16(st + woB0 + 16, Bp0 + (size_t)ns * 32 + 8);
            CP_ASYNC16(st + woB1,      Bp1 + (size_t)ns * 32);
            CP_ASYNC16(st + woB1 + 16, Bp1 + (size_t)ns * 32 + 8);
            CP_COMMIT();
        } else {
            CP_COMMIT();
        }

        uint32_t ab = sb + (uint32_t)(s & 3) * STAGE_B;
        uint32_t bb = ab + ATILE_B;

        #pragma unroll
        for (int kk = 0; kk < 2; kk++) {
            uint32_t a[4][4], b[4][4];
            const int kc = kk * 2 + (oct >> 1);
            #pragma unroll
            for (int mi = 0; mi < 4; mi++) {
                int r = wm + mi * 16 + (oct & 1) * 8 + orow;
                LDM_X4(a[mi][0], a[mi][1], a[mi][2], a[mi][3],
                       ab + (uint32_t)r * APITCH + kc * 16);
            }
            #pragma unroll
            for (int nj = 0; nj < 4; nj++) {
                int r = wn + nj * 16 + (oct & 1) * 8 + orow;
                LDM_X4(b[nj][0], b[nj][1], b[nj][2], b[nj][3],
                       bb + (uint32_t)r * APITCH + kc * 16);
            }
            #pragma unroll
            for (int mi = 0; mi < 4; mi++) {
                #pragma unroll
                for (int nj = 0; nj < 4; nj++) {
                    mma_f16(acc[mi][nj * 2 + 0], a[mi], b[nj][0], b[nj][2]);
                    mma_f16(acc[mi][nj * 2 + 1], a[mi], b[nj][1], b[nj][3]);
                }
            }
        }
    }

    #pragma unroll
    for (int mi = 0; mi < 4; mi++) {
        int m = m0 + wm + mi * 16 + gr;
        #pragma unroll
        for (int ni = 0; ni < 8; ni++) {
            int n = n0 + wn + ni * 8 + 2 * q;
            float2 v0 = make_float2(acc[mi][ni][0], acc[mi][ni][1]);
            float2 v1 = make_float2(acc[mi][ni][2], acc[mi][ni][3]);
            if (BIAS) {
                float2 bv = *(const float2*)(bias + n);
                v0.x += bv.x; v0.y += bv.y;
                v1.x += bv.x; v1.y += bv.y;
            }
            if (RES) {
                float2 r0 = *(const float2*)(res + (size_t)m * Nn + n);
                float2 r1 = *(const float2*)(res + (size_t)(m + 8) * Nn + n);
                v0.x += r0.x; v0.y += r0.y;
                v1.x += r1.x; v1.y += r1.y;
            }
            if (HOUT) {
                __half* Ch = (__half*)Cc;
                *(__half2*)(Ch + (size_t)m * Nn + n)       = __floats2half2_rn(v0.x, v0.y);
                *(__half2*)(Ch + (size_t)(m + 8) * Nn + n) = __floats2half2_rn(v1.x, v1.y);
            } else {
                float* Cf = (float*)Cc;
                *(float2*)(Cf + (size_t)m * Nn + n) = v0;
                *(float2*)(Cf + (size_t)(m + 8) * Nn + n) = v1;
            }
        }
    }
}

// ---------------- tensor-core causal flash attention --------------------------
// BR=128 (8 warps x 16 rows), BC=64. fp16 mma, fp32 softmax/accum.
#define FA_BR 128
#define FA_BC 64
#define FA_PITCH 72                    // halves per smem row (144B)

__global__ void __launch_bounds__(256, 2) flash16_k(
    const __half* __restrict__ qkv, __half* __restrict__ O)
{
    __shared__ __half Qs[FA_BR * FA_PITCH];
    __shared__ __half Ks[FA_BC * FA_PITCH];
    __shared__ __half Vs[FA_BC * FA_PITCH];

    const int qt = (int)gridDim.x - 1 - (int)blockIdx.x;   // heavy tiles first
    const int bh = blockIdx.y;
    const int b = bh >> 4, h = bh & 15;
    const int tid = threadIdx.x, warp = tid >> 5, lane = tid & 31;
    const int gr = lane >> 2, q = lane & 3;
    const int wq = warp * 16;
    const int qr0 = qt * FA_BR;

    const uint32_t qb = smem_u32(Qs);
    const uint32_t kb = smem_u32(Ks);
    const uint32_t vb = smem_u32(Vs);

    const size_t rstride = 3 * C_;
    const __half* qbase = qkv + (size_t)(b * N_) * rstride + h * D_;

    // load Q tile (128 rows x 64 halves)
    #pragma unroll
    for (int i = 0; i < 4; i++) {
        int idx = tid + i * 256;
        int r = idx >> 3, c = idx & 7;
        *(uint4*)(Qs + r * FA_PITCH + c * 8) =
            *(const uint4*)(qbase + (size_t)(qr0 + r) * rstride + c * 8);
    }
    __syncthreads();

    // preload Q A-fragments (whole 16x64 warp slab)
    uint32_t qa[4][4];
    {
        int r = wq + (lane & 15);
        #pragma unroll
        for (int kc = 0; kc < 4; kc++) {
            int ch = kc * 2 + (lane >> 4);
            LDM_X4(qa[kc][0], qa[kc][1], qa[kc][2], qa[kc][3],
                   qb + (uint32_t)(r * FA_PITCH + ch * 8) * 2);
        }
    }

    float m0 = -INFINITY, m1 = -INFINITY, l0 = 0.f, l1 = 0.f;
    float o[8][4];
    #pragma unroll
    for (int i = 0; i < 8; i++)
        #pragma unroll
        for (int j = 0; j < 4; j++) o[i][j] = 0.f;

    const int row0 = qr0 + wq + gr;
    const int row1 = row0 + 8;
    const int nkt = 2 * qt + 2;

    for (int kt = 0; kt < nkt; kt++) {
        __syncthreads();
        const __half* kbase = qkv + (size_t)(b * N_ + kt * FA_BC) * rstride + C_ + h * D_;
        #pragma unroll
        for (int i = 0; i < 2; i++) {
            int idx = tid + i * 256;
            int r = idx >> 3, c = idx & 7;
            *(uint4*)(Ks + r * FA_PITCH + c * 8) =
                *(const uint4*)(kbase + (size_t)r * rstride + c * 8);
            *(uint4*)(Vs + r * FA_PITCH + c * 8) =
                *(const uint4*)(kbase + (size_t)r * rstride + C_ + c * 8);
        }
        __syncthreads();

        // S = Q @ K^T  (16 x 64 per warp)
        float sc[8][4];
        #pragma unroll
        for (int i = 0; i < 8; i++)
            #pragma unroll
            for (int j = 0; j < 4; j++) sc[i][j] = 0.f;

        {
            int rk = (lane & 15);
            #pragma unroll
            for (int kc = 0; kc < 4; kc++) {
                int ch = kc * 2 + (lane >> 4);
                #pragma unroll
                for (int nj = 0; nj < 4; nj++) {
                    uint32_t b0, b1, b2, b3;
                    LDM_X4(b0, b1, b2, b3,
                           kb + (uint32_t)((nj * 16 + rk) * FA_PITCH + ch * 8) * 2);
                    mma_f16(sc[nj * 2 + 0], qa[kc], b0, b2);
                    mma_f16(sc[nj * 2 + 1], qa[kc], b1, b3);
                }
            }
        }

        // scale + causal mask + row max
        const bool need_mask = (kt * FA_BC + FA_BC - 1) > (qr0 + wq);
        float mt0 = -INFINITY, mt1 = -INFINITY;
        #pragma unroll
        for (int nt = 0; nt < 8; nt++) {
            int key = kt * FA_BC + nt * 8 + 2 * q;
            #pragma unroll
            for (int j = 0; j < 4; j++) {
                float s = sc[nt][j] * 0.125f;
                if (need_mask) {
                    int k_ = key + (j & 1);
                    int r_ = (j < 2) ? row0 : row1;
                    if (k_ > r_) s = -INFINITY;
                }
                sc[nt][j] = s;
            }
            mt0 = fmaxf(mt0, fmaxf(sc[nt][0], sc[nt][1]));
            mt1 = fmaxf(mt1, fmaxf(sc[nt][2], sc[nt][3]));
        }
        mt0 = fmaxf(mt0, __shfl_xor_sync(0xffffffffu, mt0, 1));
        mt0 = fmaxf(mt0, __shfl_xor_sync(0xffffffffu, mt0, 2));
        mt1 = fmaxf(mt1, __shfl_xor_sync(0xffffffffu, mt1, 1));
        mt1 = fmaxf(mt1, __shfl_xor_sync(0xffffffffu, mt1, 2));

        float nm0 = fmaxf(m0, mt0), nm1 = fmaxf(m1, mt1);
        float corr0 = __expf(m0 - nm0), corr1 = __expf(m1 - nm1);
        m0 = nm0; m1 = nm1;
        #pragma unroll
        for (int nt = 0; nt < 8; nt++) {
            o[nt][0] *= corr0; o[nt][1] *= corr0;
            o[nt][2] *= corr1; o[nt][3] *= corr1;
        }
        l0 *= corr0; l1 *= corr1;

        // per-16-key group: exponentiate, pack P, P @ V
        #pragma unroll
        for (int kg = 0; kg < 4; kg++) {
            float p00 = __expf(sc[2*kg][0]   - nm0), p01 = __expf(sc[2*kg][1]   - nm0);
            float p10 = __expf(sc[2*kg][2]   - nm1), p11 = __expf(sc[2*kg][3]   - nm1);
            float p20 = __expf(sc[2*kg+1][0] - nm0), p21 = __expf(sc[2*kg+1][1] - nm0);
            float p30 = __expf(sc[2*kg+1][2] - nm1), p31 = __expf(sc[2*kg+1][3] - nm1);
            l0 += p00 + p01 + p20 + p21;
            l1 += p10 + p11 + p30 + p31;
            uint32_t P[4];
            P[0] = h2_u32(__floats2half2_rn(p00, p01));
            P[1] = h2_u32(__floats2half2_rn(p10, p11));
            P[2] = h2_u32(__floats2half2_rn(p20, p21));
            P[3] = h2_u32(__floats2half2_rn(p30, p31));
            int rv = kg * 16 + (lane & 15);
            #pragma unroll
            for (int dj = 0; dj < 4; dj++) {
                uint32_t v0, v1, v2, v3;
                LDM_X4_T(v0, v1, v2, v3,
                         vb + (uint32_t)(rv * FA_PITCH + (dj * 2 + (lane >> 4)) * 8) * 2);
                mma_f16(o[dj * 2 + 0], P, v0, v1);
                mma_f16(o[dj * 2 + 1], P, v2, v3);
            }
        }
    }

    // l is a row quantity — sum partials across the quad.
    l0 += __shfl_xor_sync(0xffffffffu, l0, 1);
    l0 += __shfl_xor_sync(0xffffffffu, l0, 2);
    l1 += __shfl_xor_sync(0xffffffffu, l1, 1);
    l1 += __shfl_xor_sync(0xffffffffu, l1, 2);

    float inv0 = 1.f / l0, inv1 = 1.f / l1;
    __half* ob = O + (size_t)(b * N_) * C_ + h * D_;
    #pragma unroll
    for (int nt = 0; nt < 8; nt++) {
        int d = nt * 8 + 2 * q;
        *(__half2*)(ob + (size_t)row0 * C_ + d) =
            __floats2half2_rn(o[nt][0] * inv0, o[nt][1] * inv0);
        *(__half2*)(ob + (size_t)row1 * C_ + d) =
            __floats2half2_rn(o[nt][2] * inv1, o[nt][3] * inv1);
    }
}

// ---------------- silu(a) * b (half in/out) ----------------------------------
__global__ void __launch_bounds__(256) silu_mul_k(
    const __half* __restrict__ a, const __half* __restrict__ bb,
    __half* __restrict__ out, int n8)
{
    int i = blockIdx.x * 256 + threadIdx.x;
    if (i < n8) {
        uint4 av = ((const uint4*)a)[i];
        uint4 bv = ((const uint4*)bb)[i];
        uint32_t* ap = (uint32_t*)&av;
        uint32_t* bp = (uint32_t*)&bv;
        uint4 ov;
        uint32_t* op = (uint32_t*)&ov;
        #pragma unroll
        for (int j = 0; j < 4; j++) {
            float2 af = __half22float2(u32_h2(ap[j]));
            float2 bf = __half22float2(u32_h2(bp[j]));
            float ox = af.x / (1.f + __expf(-af.x)) * bf.x;
            float oy = af.y / (1.f + __expf(-af.y)) * bf.y;
            op[j] = h2_u32(__floats2half2_rn(ox, oy));
        }
        ((uint4*)out)[i] = ov;
    }
}

// ---------------- launcher ---------------------------------------------------
extern "C" void kernel_launch(void* const* d_in, const int* in_sizes, int n_in,
                              void* d_out, int out_size)
{
    const float* x      = (const float*)d_in[0];
    const float* qkv_w  = (const float*)d_in[2];
    const float* qkv_b  = (const float*)d_in[3];
    const float* proj_w = (const float*)d_in[4];
    const float* proj_b = (const float*)d_in[5];
    const float* ln1_g  = (const float*)d_in[6];
    const float* ln1_b  = (const float*)d_in[7];
    const float* ln2_g  = (const float*)d_in[8];
    const float* ln2_b  = (const float*)d_in[9];
    const float* w1     = (const float*)d_in[10];
    const float* w2     = (const float*)d_in[11];
    const float* w3     = (const float*)d_in[12];
    float* out = (float*)d_out;

    float *x1;
    __half *hh, *qkvh, *oh, *ah, *bh, *wq, *wp, *tw1, *tw2, *tw3;
    cudaGetSymbolAddress((void**)&x1,   g_x1);
    cudaGetSymbolAddress((void**)&hh,   g_hh);
    cudaGetSymbolAddress((void**)&qkvh, g_qkvh);
    cudaGetSymbolAddress((void**)&oh,   g_oh);
    cudaGetSymbolAddress((void**)&ah,   g_ah);
    cudaGetSymbolAddress((void**)&bh,   g_bh);
    cudaGetSymbolAddress((void**)&wq,   g_wqh);
    cudaGetSymbolAddress((void**)&wp,   g_wph);
    cudaGetSymbolAddress((void**)&tw1,  g_w1h);
    cudaGetSymbolAddress((void**)&tw2,  g_w2h);
    cudaGetSymbolAddress((void**)&tw3,  g_w3h);

    cudaFuncSetAttribute(hgemm<true,  false, true >, cudaFuncAttributeMaxDynamicSharedMemorySize, HSMEM_BYTES);
    cudaFuncSetAttribute(hgemm<true,  true,  false>, cudaFuncAttributeMaxDynamicSharedMemorySize, HSMEM_BYTES);
    cudaFuncSetAttribute(hgemm<false, false, true >, cudaFuncAttributeMaxDynamicSharedMemorySize, HSMEM_BYTES);
    cudaFuncSetAttribute(hgemm<false, true,  false>, cudaFuncAttributeMaxDynamicSharedMemorySize, HSMEM_BYTES);

    // 0) weights -> fp16 (rn)
    cvt_half_k<<<(3*C_*C_/4 + 255)/256, 256>>>(qkv_w,  wq,  3*C_*C_/4);
    cvt_half_k<<<(C_*C_/4   + 255)/256, 256>>>(proj_w, wp,  C_*C_/4);
    cvt_half_k<<<(FF_*C_/4  + 255)/256, 256>>>(w1,     tw1, FF_*C_/4);
    cvt_half_k<<<(C_*FF_/4  + 255)/256, 256>>>(w2,     tw2, C_*FF_/4);
    cvt_half_k<<<(FF_*C_/4  + 255)/256, 256>>>(w3,     tw3, FF_*C_/4);

    // 1) hh = LN1(x)
    layernorm_k<<<M_, 256>>>(x, ln1_g, ln1_b, hh);
    // 2) qkvh = hh @ qkv_w^T + qkv_b  (half out)
    hgemm<true, false, true><<<dim3(3*C_/256, M_/128), 256, HSMEM_BYTES>>>(
        hh, wq, qkv_b, nullptr, qkvh, M_, 3*C_, C_);
    // 3) oh = causal_attention(qkvh)
    flash16_k<<<dim3(N_/FA_BR, B_*H_), 256>>>(qkvh, oh);
    // 4) x1 = x + oh @ proj_w^T + proj_b  (fp32 out)
    hgemm<true, true, false><<<dim3(C_/256, M_/128), 256, HSMEM_BYTES>>>(
        oh, wp, proj_b, x, x1, M_, C_, C_);
    // 5) hh = LN2(x1)
    layernorm_k<<<M_, 256>>>(x1, ln2_g, ln2_b, hh);
    // 6) ah = hh @ w1^T ; bh = hh @ w3^T  (half out)
    hgemm<false, false, true><<<dim3(FF_/256, M_/128), 256, HSMEM_BYTES>>>(
        hh, tw1, nullptr, nullptr, ah, M_, FF_, C_);
    hgemm<false, false, true><<<dim3(FF_/256, M_/128), 256, HSMEM_BYTES>>>(
        hh, tw3, nullptr, nullptr, bh, M_, FF_, C_);
    // 7) ah = silu(ah) * bh
    silu_mul_k<<<(M_*FF_/8 + 255)/256, 256>>>(ah, bh, ah, M_*FF_/8);
    // 8) out = x1 + ah @ w2^T  (fp32 out)
    hgemm<false, true, false><<<dim3(C_/256, M_/128), 256, HSMEM_BYTES>>>(
        ah, tw2, nullptr, x1, out, M_, C_, FF_);
}

// round 14
// speedup vs baseline: 1.0320x; 1.0320x over previous
#include <cuda_runtime.h>
#include <cuda_fp16.h>
#include <math.h>
#include <stdint.h>

#define B_ 4
#define N_ 2048
#define C_ 1024
#define H_ 16
#define D_ 64
#define FF_ 4096
#define M_ (B_ * N_)   // 8192 rows

// ---------------- scratch ----------------------------------------------------
__device__ float  g_x1 [M_ * C_];      // residual after attention (fp32)
__device__ __half g_hh [M_ * C_];      // LN output (half)
__device__ __half g_qkvh[M_ * 3 * C_]; // qkv projections (half)
__device__ __half g_oh [M_ * C_];      // attention output (half)
__device__ __half g_ah [M_ * FF_];     // h@w1^T (half)
__device__ __half g_bh [M_ * FF_];     // silu(ah) * (h@w3^T) (half)
// fp16 weights
__device__ __half g_wqh[3 * C_ * C_];
__device__ __half g_wph[C_ * C_];
__device__ __half g_w1h[FF_ * C_];
__device__ __half g_w2h[C_ * FF_];
__device__ __half g_w3h[FF_ * C_];

// ---------------- helpers ----------------------------------------------------
__device__ __forceinline__ uint32_t smem_u32(const void* p) {
    uint32_t a;
    asm("{ .reg .u64 t; cvta.to.shared.u64 t, %1; cvt.u32.u64 %0, t; }" : "=r"(a) : "l"(p));
    return a;
}
__device__ __forceinline__ uint32_t h2_u32(__half2 h) {
    return *reinterpret_cast<uint32_t*>(&h);
}
__device__ __forceinline__ __half2 u32_h2(uint32_t u) {
    return *reinterpret_cast<__half2*>(&u);
}
#define CP_ASYNC16(dst, src) \
    asm volatile("cp.async.cg.shared.global [%0], [%1], 16;" :: "r"(dst), "l"(src))
#define CP_COMMIT() asm volatile("cp.async.commit_group;" ::: "memory")
#define CP_WAIT(n)  asm volatile("cp.async.wait_group %0;" :: "n"(n) : "memory")

#define LDM_X4(r0, r1, r2, r3, addr) \
    asm volatile("ldmatrix.sync.aligned.m8n8.x4.shared.b16 {%0,%1,%2,%3}, [%4];" \
                 : "=r"(r0), "=r"(r1), "=r"(r2), "=r"(r3) : "r"(addr))
#define LDM_X4_T(r0, r1, r2, r3, addr) \
    asm volatile("ldmatrix.sync.aligned.m8n8.x4.trans.shared.b16 {%0,%1,%2,%3}, [%4];" \
                 : "=r"(r0), "=r"(r1), "=r"(r2), "=r"(r3) : "r"(addr))

__device__ __forceinline__ void mma_f16(float* c, const uint32_t* a,
                                        uint32_t b0, uint32_t b1) {
    asm volatile(
        "mma.sync.aligned.m16n8k16.row.col.f32.f16.f16.f32 "
        "{%0,%1,%2,%3}, {%4,%5,%6,%7}, {%8,%9}, {%0,%1,%2,%3};"
        : "+f"(c[0]), "+f"(c[1]), "+f"(c[2]), "+f"(c[3])
        : "r"(a[0]), "r"(a[1]), "r"(a[2]), "r"(a[3]), "r"(b0), "r"(b1));
}

// ---------------- fused fp32 -> fp16 weight conversion -----------------------
// one launch converts all 5 weight matrices (indices in float4 units)
#define CVT_N0 786432              // qkv_w  3M floats
#define CVT_N1 (CVT_N0 + 262144)   // proj_w 1M
#define CVT_N2 (CVT_N1 + 1048576)  // w1     4M
#define CVT_N3 (CVT_N2 + 1048576)  // w2     4M
#define CVT_N4 (CVT_N3 + 1048576)  // w3     4M

__global__ void __launch_bounds__(256) cvt_all_k(
    const float* __restrict__ s0, __half* __restrict__ d0,
    const float* __restrict__ s1, __half* __restrict__ d1,
    const float* __restrict__ s2, __half* __restrict__ d2,
    const float* __restrict__ s3, __half* __restrict__ d3,
    const float* __restrict__ s4, __half* __restrict__ d4)
{
    int i = blockIdx.x * 256 + threadIdx.x;
    const float* s; __half* d; int base;
    if      (i < CVT_N0) { s = s0; d = d0; base = 0; }
    else if (i < CVT_N1) { s = s1; d = d1; base = CVT_N0; }
    else if (i < CVT_N2) { s = s2; d = d2; base = CVT_N1; }
    else if (i < CVT_N3) { s = s3; d = d3; base = CVT_N2; }
    else                 { s = s4; d = d4; base = CVT_N3; }
    int j = i - base;
    float4 v = ((const float4*)s)[j];
    __half2* o = (__half2*)d + j * 2;
    o[0] = __floats2half2_rn(v.x, v.y);
    o[1] = __floats2half2_rn(v.z, v.w);
}

// ---------------- LayerNorm (half output) ------------------------------------
__global__ void __launch_bounds__(256) layernorm_k(
    const float* __restrict__ x, const float* __restrict__ gam,
    const float* __restrict__ bet, __half* __restrict__ out)
{
    int row = blockIdx.x;
    const float* xr = x + (size_t)row * C_;
    __half2* orow = (__half2*)(out + (size_t)row * C_);
    int t = threadIdx.x;

    float4 v = *(const float4*)(xr + t * 4);
    float s1 = v.x + v.y + v.z + v.w;
    float s2 = v.x*v.x + v.y*v.y + v.z*v.z + v.w*v.w;
    #pragma unroll
    for (int o = 16; o; o >>= 1) {
        s1 += __shfl_xor_sync(0xffffffffu, s1, o);
        s2 += __shfl_xor_sync(0xffffffffu, s2, o);
    }
    __shared__ float r1[8], r2[8];
    __shared__ float mu_s, rs_s;
    if ((t & 31) == 0) { r1[t >> 5] = s1; r2[t >> 5] = s2; }
    __syncthreads();
    if (t == 0) {
        float a = 0.f, b = 0.f;
        #pragma unroll
        for (int i = 0; i < 8; i++) { a += r1[i]; b += r2[i]; }
        float mu = a * (1.f / C_);
        float var = b * (1.f / C_) - mu * mu;
        mu_s = mu; rs_s = rsqrtf(var + 1e-6f);
    }
    __syncthreads();
    float mu = mu_s, rs = rs_s;
    float4 gv = *(const float4*)(gam + t * 4);
    float4 bv = *(const float4*)(bet + t * 4);
    float ox = (v.x - mu) * rs * gv.x + bv.x;
    float oy = (v.y - mu) * rs * gv.y + bv.y;
    float oz = (v.z - mu) * rs * gv.z + bv.z;
    float ow = (v.w - mu) * rs * gv.w + bv.w;
    orow[t * 2 + 0] = __floats2half2_rn(ox, oy);
    orow[t * 2 + 1] = __floats2half2_rn(oz, ow);
}

// ---------------- fp16 mma GEMM: C = A(MxK)*B(NxK)^T (+bias)(+res)(+silu) ----
// 128x128 tile, BK=32 halves, 4-stage cp.async, 256 threads, warp tile 64x32.
// SILU: out = silu(sa[m][n]) * acc  (for the gated-MLP fusion)
#define APITCH 80                      // bytes per smem row (64B data + 16B pad)
#define ATILE_B (128 * APITCH)         // 10240
#define STAGE_B (2 * ATILE_B)          // 20480
#define HSMEM_BYTES (4 * STAGE_B)      // 81920

template<bool BIAS, bool RES, bool HOUT, bool SILU>
__global__ void __launch_bounds__(256, 2) hgemm(
    const __half* __restrict__ A, const __half* __restrict__ Bm,
    const float* __restrict__ bias, const float* __restrict__ res,
    const __half* __restrict__ sa,
    void* __restrict__ Cc, int M, int Nn, int K)
{
    extern __shared__ char smc[];
    uint32_t sb = smem_u32(smc);
    const int tid = threadIdx.x;
    const int warp = tid >> 5, lane = tid & 31;
    const int m0 = blockIdx.y * 128, n0 = blockIdx.x * 128;
    const int wm = (warp >> 2) * 64, wn = (warp & 3) * 32;
    const int gr = lane >> 2, q = lane & 3;
    const int oct = lane >> 3, orow = lane & 7;

    const int lrow = tid >> 1;
    const int lc = (tid & 1) * 2;
    const __half* Ap = A  + (size_t)(m0 + lrow) * K + lc * 8;
    const __half* Bp = Bm + (size_t)(n0 + lrow) * K + lc * 8;
    const uint32_t woA = (uint32_t)lrow * APITCH + lc * 16;
    const uint32_t woB = woA + ATILE_B;

    float acc[4][4][4];
    #pragma unroll
    for (int i = 0; i < 4; i++)
        #pragma unroll
        for (int j = 0; j < 4; j++)
            #pragma unroll
            for (int c = 0; c < 4; c++) acc[i][j][c] = 0.f;

    const int NS = K >> 5;

    #pragma unroll
    for (int s = 0; s < 3; s++) {
        uint32_t st = sb + (uint32_t)s * STAGE_B;
        CP_ASYNC16(st + woA,      Ap + (size_t)s * 32);
        CP_ASYNC16(st + woA + 16, Ap + (size_t)s * 32 + 8);
        CP_ASYNC16(st + woB,      Bp + (size_t)s * 32);
        CP_ASYNC16(st + woB + 16, Bp + (size_t)s * 32 + 8);
        CP_COMMIT();
    }

    for (int s = 0; s < NS; s++) {
        CP_WAIT(2);
        __syncthreads();

        int ns = s + 3;
        if (ns < NS) {
            uint32_t st = sb + (uint32_t)(ns & 3) * STAGE_B;
            CP_ASYNC16(st + woA,      Ap + (size_t)ns * 32);
            CP_ASYNC16(st + woA + 16, Ap + (size_t)ns * 32 + 8);
            CP_ASYNC16(st + woB,      Bp + (size_t)ns * 32);
            CP_ASYNC16(st + woB + 16, Bp + (size_t)ns * 32 + 8);
            CP_COMMIT();
        } else {
            CP_COMMIT();
        }

        uint32_t ab = sb + (uint32_t)(s & 3) * STAGE_B;
        uint32_t bb = ab + ATILE_B;

        #pragma unroll
        for (int kk = 0; kk < 2; kk++) {
            uint32_t a[4][4], b[2][4];
            const int kc = kk * 2 + (oct >> 1);
            #pragma unroll
            for (int mi = 0; mi < 4; mi++) {
                int r = wm + mi * 16 + (oct & 1) * 8 + orow;
                LDM_X4(a[mi][0], a[mi][1], a[mi][2], a[mi][3],
                       ab + (uint32_t)r * APITCH + kc * 16);
            }
            #pragma unroll
            for (int nj = 0; nj < 2; nj++) {
                int r = wn + nj * 16 + (oct & 1) * 8 + orow;
                LDM_X4(b[nj][0], b[nj][1], b[nj][2], b[nj][3],
                       bb + (uint32_t)r * APITCH + kc * 16);
            }
            #pragma unroll
            for (int mi = 0; mi < 4; mi++) {
                #pragma unroll
                for (int nj = 0; nj < 2; nj++) {
                    mma_f16(acc[mi][nj * 2 + 0], a[mi], b[nj][0], b[nj][2]);
                    mma_f16(acc[mi][nj * 2 + 1], a[mi], b[nj][1], b[nj][3]);
                }
            }
        }
    }

    #pragma unroll
    for (int mi = 0; mi < 4; mi++) {
        int m = m0 + wm + mi * 16 + gr;
        #pragma unroll
        for (int ni = 0; ni < 4; ni++) {
            int n = n0 + wn + ni * 8 + 2 * q;
            float2 v0 = make_float2(acc[mi][ni][0], acc[mi][ni][1]);
            float2 v1 = make_float2(acc[mi][ni][2], acc[mi][ni][3]);
            if (BIAS) {
                float2 bv = *(const float2*)(bias + n);
                v0.x += bv.x; v0.y += bv.y;
                v1.x += bv.x; v1.y += bv.y;
            }
            if (RES) {
                float2 r0 = *(const float2*)(res + (size_t)m * Nn + n);
                float2 r1 = *(const float2*)(res + (size_t)(m + 8) * Nn + n);
                v0.x += r0.x; v0.y += r0.y;
                v1.x += r1.x; v1.y += r1.y;
            }
            if (SILU) {
                float2 a0 = __half22float2(*(const __half2*)(sa + (size_t)m * Nn + n));
                float2 a1 = __half22float2(*(const __half2*)(sa + (size_t)(m + 8) * Nn + n));
                v0.x *= a0.x / (1.f + __expf(-a0.x));
                v0.y *= a0.y / (1.f + __expf(-a0.y));
                v1.x *= a1.x / (1.f + __expf(-a1.x));
                v1.y *= a1.y / (1.f + __expf(-a1.y));
            }
            if (HOUT) {
                __half* Ch = (__half*)Cc;
                *(__half2*)(Ch + (size_t)m * Nn + n)       = __floats2half2_rn(v0.x, v0.y);
                *(__half2*)(Ch + (size_t)(m + 8) * Nn + n) = __floats2half2_rn(v1.x, v1.y);
            } else {
                float* Cf = (float*)Cc;
                *(float2*)(Cf + (size_t)m * Nn + n) = v0;
                *(float2*)(Cf + (size_t)(m + 8) * Nn + n) = v1;
            }
        }
    }
}

// ---------------- tensor-core causal flash attention --------------------------
// BR=128 (8 warps x 16 rows), BC=64. fp16 mma, fp32 softmax/accum.
// K/V tiles double-buffered via cp.async: prefetch tile kt+1 during compute kt.
#define FA_BR 128
#define FA_BC 64
#define FA_PITCH 72                    // halves per smem row (144B)

__global__ void __launch_bounds__(256, 2) flash16_k(
    const __half* __restrict__ qkv, __half* __restrict__ O)
{
    __shared__ __half Qs[FA_BR * FA_PITCH];
    __shared__ __half Ks[2][FA_BC * FA_PITCH];
    __shared__ __half Vs[2][FA_BC * FA_PITCH];

    const int qt = (int)gridDim.x - 1 - (int)blockIdx.x;   // heavy tiles first
    const int bh = blockIdx.y;
    const int b = bh >> 4, h = bh & 15;
    const int tid = threadIdx.x, warp = tid >> 5, lane = tid & 31;
    const int gr = lane >> 2, q = lane & 3;
    const int wq = warp * 16;
    const int qr0 = qt * FA_BR;

    const uint32_t qb = smem_u32(Qs);
    const uint32_t kb2[2] = { smem_u32(Ks[0]), smem_u32(Ks[1]) };
    const uint32_t vb2[2] = { smem_u32(Vs[0]), smem_u32(Vs[1]) };

    const size_t rstride = 3 * C_;
    const __half* base0 = qkv + (size_t)(b * N_) * rstride;
    const int nkt = 2 * qt + 2;

    // per-thread K/V load geometry (two 16B chunks per tile per array)
    const int lr0 = tid >> 3, lcc = (tid & 7) * 8;         // rows 0..31
    const int lr1 = lr0 + 32;
    const uint32_t so0 = ((uint32_t)lr0 * FA_PITCH + lcc) * 2;
    const uint32_t so1 = ((uint32_t)lr1 * FA_PITCH + lcc) * 2;

    // prefetch tile 0 (K,V) via cp.async
    {
        const __half* kbase = base0 + C_ + h * D_;
        CP_ASYNC16(kb2[0] + so0, kbase + (size_t)lr0 * rstride + lcc);
        CP_ASYNC16(kb2[0] + so1, kbase + (size_t)lr1 * rstride + lcc);
        CP_ASYNC16(vb2[0] + so0, kbase + (size_t)lr0 * rstride + C_ + lcc);
        CP_ASYNC16(vb2[0] + so1, kbase + (size_t)lr1 * rstride + C_ + lcc);
        CP_COMMIT();
    }

    // load Q tile (128 rows x 64 halves) directly
    const __half* qbase = base0 + h * D_;
    #pragma unroll
    for (int i = 0; i < 4; i++) {
        int idx = tid + i * 256;
        int r = idx >> 3, c = idx & 7;
        *(uint4*)(Qs + r * FA_PITCH + c * 8) =
            *(const uint4*)(qbase + (size_t)(qr0 + r) * rstride + c * 8);
    }
    __syncthreads();

    // preload Q A-fragments (whole 16x64 warp slab)
    uint32_t qa[4][4];
    {
        int r = wq + (lane & 15);
        #pragma unroll
        for (int kc = 0; kc < 4; kc++) {
            int ch = kc * 2 + (lane >> 4);
            LDM_X4(qa[kc][0], qa[kc][1], qa[kc][2], qa[kc][3],
                   qb + (uint32_t)(r * FA_PITCH + ch * 8) * 2);
        }
    }

    float m0 = -INFINITY, m1 = -INFINITY, l0 = 0.f, l1 = 0.f;
    float o[8][4];
    #pragma unroll
    for (int i = 0; i < 8; i++)
        #pragma unroll
        for (int j = 0; j < 4; j++) o[i][j] = 0.f;

    const int row0 = qr0 + wq + gr;
    const int row1 = row0 + 8;

    for (int kt = 0; kt < nkt; kt++) {
        CP_WAIT(0);
        __syncthreads();            // tile kt resident; prev compute done

        int nb = kt + 1;
        if (nb < nkt) {
            const __half* kbase = base0 + (size_t)(nb * FA_BC) * rstride + C_ + h * D_;
            uint32_t kbn = kb2[nb & 1], vbn = vb2[nb & 1];
            CP_ASYNC16(kbn + so0, kbase + (size_t)lr0 * rstride + lcc);
            CP_ASYNC16(kbn + so1, kbase + (size_t)lr1 * rstride + lcc);
            CP_ASYNC16(vbn + so0, kbase + (size_t)lr0 * rstride + C_ + lcc);
            CP_ASYNC16(vbn + so1, kbase + (size_t)lr1 * rstride + C_ + lcc);
            CP_COMMIT();
        } else {
            CP_COMMIT();
        }

        const uint32_t kb = kb2[kt & 1];
        const uint32_t vb = vb2[kt & 1];

        // S = Q @ K^T  (16 x 64 per warp)
        float sc[8][4];
        #pragma unroll
        for (int i = 0; i < 8; i++)
            #pragma unroll
            for (int j = 0; j < 4; j++) sc[i][j] = 0.f;

        {
            int rk = (lane & 15);
            #pragma unroll
            for (int kc = 0; kc < 4; kc++) {
                int ch = kc * 2 + (lane >> 4);
                #pragma unroll
                for (int nj = 0; nj < 4; nj++) {
                    uint32_t b0, b1, b2, b3;
                    LDM_X4(b0, b1, b2, b3,
                           kb + (uint32_t)((nj * 16 + rk) * FA_PITCH + ch * 8) * 2);
                    mma_f16(sc[nj * 2 + 0], qa[kc], b0, b2);
                    mma_f16(sc[nj * 2 + 1], qa[kc], b1, b3);
                }
            }
        }

        // scale + causal mask + row max
        const bool need_mask = (kt * FA_BC + FA_BC - 1) > (qr0 + wq);
        float mt0 = -INFINITY, mt1 = -INFINITY;
        #pragma unroll
        for (int nt = 0; nt < 8; nt++) {
            int key = kt * FA_BC + nt * 8 + 2 * q;
            #pragma unroll
            for (int j = 0; j < 4; j++) {
                float s = sc[nt][j] * 0.125f;
                if (need_mask) {
                    int k_ = key + (j & 1);
                    int r_ = (j < 2) ? row0 : row1;
                    if (k_ > r_) s = -INFINITY;
                }
                sc[nt][j] = s;
            }
            mt0 = fmaxf(mt0, fmaxf(sc[nt][0], sc[nt][1]));
            mt1 = fmaxf(mt1, fmaxf(sc[nt][2], sc[nt][3]));
        }
        mt0 = fmaxf(mt0, __shfl_xor_sync(0xffffffffu, mt0, 1));
        mt0 = fmaxf(mt0, __shfl_xor_sync(0xffffffffu, mt0, 2));
        mt1 = fmaxf(mt1, __shfl_xor_sync(0xffffffffu, mt1, 1));
        mt1 = fmaxf(mt1, __shfl_xor_sync(0xffffffffu, mt1, 2));

        float nm0 = fmaxf(m0, mt0), nm1 = fmaxf(m1, mt1);
        float corr0 = __expf(m0 - nm0), corr1 = __expf(m1 - nm1);
        m0 = nm0; m1 = nm1;
        #pragma unroll
        for (int nt = 0; nt < 8; nt++) {
            o[nt][0] *= corr0; o[nt][1] *= corr0;
            o[nt][2] *= corr1; o[nt][3] *= corr1;
        }
        l0 *= corr0; l1 *= corr1;

        // per-16-key group: exponentiate, pack P, P @ V
        #pragma unroll
        for (int kg = 0; kg < 4; kg++) {
            float p00 = __expf(sc[2*kg][0]   - nm0), p01 = __expf(sc[2*kg][1]   - nm0);
            float p10 = __expf(sc[2*kg][2]   - nm1), p11 = __expf(sc[2*kg][3]   - nm1);
            float p20 = __expf(sc[2*kg+1][0] - nm0), p21 = __expf(sc[2*kg+1][1] - nm0);
            float p30 = __expf(sc[2*kg+1][2] - nm1), p31 = __expf(sc[2*kg+1][3] - nm1);
            l0 += p00 + p01 + p20 + p21;
            l1 += p10 + p11 + p30 + p31;
            uint32_t P[4];
            P[0] = h2_u32(__floats2half2_rn(p00, p01));
            P[1] = h2_u32(__floats2half2_rn(p10, p11));
            P[2] = h2_u32(__floats2half2_rn(p20, p21));
            P[3] = h2_u32(__floats2half2_rn(p30, p31));
            int rv = kg * 16 + (lane & 15);
            #pragma unroll
            for (int dj = 0; dj < 4; dj++) {
                uint32_t v0, v1, v2, v3;
                LDM_X4_T(v0, v1, v2, v3,
                         vb + (uint32_t)(rv * FA_PITCH + (dj * 2 + (lane >> 4)) * 8) * 2);
                mma_f16(o[dj * 2 + 0], P, v0, v1);
                mma_f16(o[dj * 2 + 1], P, v2, v3);
            }
        }
    }

    // l is a row quantity — sum partials across the quad.
    l0 += __shfl_xor_sync(0xffffffffu, l0, 1);
    l0 += __shfl_xor_sync(0xffffffffu, l0, 2);
    l1 += __shfl_xor_sync(0xffffffffu, l1, 1);
    l1 += __shfl_xor_sync(0xffffffffu, l1, 2);

    float inv0 = 1.f / l0, inv1 = 1.f / l1;
    __half* ob = O + (size_t)(b * N_) * C_ + h * D_;
    #pragma unroll
    for (int nt = 0; nt < 8; nt++) {
        int d = nt * 8 + 2 * q;
        *(__half2*)(ob + (size_t)row0 * C_ + d) =
            __floats2half2_rn(o[nt][0] * inv0, o[nt][1] * inv0);
        *(__half2*)(ob + (size_t)row1 * C_ + d) =
            __floats2half2_rn(o[nt][2] * inv1, o[nt][3] * inv1);
    }
}

// ---------------- launcher ---------------------------------------------------
extern "C" void kernel_launch(void* const* d_in, const int* in_sizes, int n_in,
                              void* d_out, int out_size)
{
    const float* x      = (const float*)d_in[0];
    const float* qkv_w  = (const float*)d_in[2];
    const float* qkv_b  = (const float*)d_in[3];
    const float* proj_w = (const float*)d_in[4];
    const float* proj_b = (const float*)d_in[5];
    const float* ln1_g  = (const float*)d_in[6];
    const float* ln1_b  = (const float*)d_in[7];
    const float* ln2_g  = (const float*)d_in[8];
    const float* ln2_b  = (const float*)d_in[9];
    const float* w1     = (const float*)d_in[10];
    const float* w2     = (const float*)d_in[11];
    const float* w3     = (const float*)d_in[12];
    float* out = (float*)d_out;

    float *x1;
    __half *hh, *qkvh, *oh, *ah, *bh, *wq, *wp, *tw1, *tw2, *tw3;
    cudaGetSymbolAddress((void**)&x1,   g_x1);
    cudaGetSymbolAddress((void**)&hh,   g_hh);
    cudaGetSymbolAddress((void**)&qkvh, g_qkvh);
    cudaGetSymbolAddress((void**)&oh,   g_oh);
    cudaGetSymbolAddress((void**)&ah,   g_ah);
    cudaGetSymbolAddress((void**)&bh,   g_bh);
    cudaGetSymbolAddress((void**)&wq,   g_wqh);
    cudaGetSymbolAddress((void**)&wp,   g_wph);
    cudaGetSymbolAddress((void**)&tw1,  g_w1h);
    cudaGetSymbolAddress((void**)&tw2,  g_w2h);
    cudaGetSymbolAddress((void**)&tw3,  g_w3h);

    cudaFuncSetAttribute(hgemm<true,  false, true,  false>, cudaFuncAttributeMaxDynamicSharedMemorySize, HSMEM_BYTES);
    cudaFuncSetAttribute(hgemm<true,  true,  false, false>, cudaFuncAttributeMaxDynamicSharedMemorySize, HSMEM_BYTES);
    cudaFuncSetAttribute(hgemm<false, false, true,  false>, cudaFuncAttributeMaxDynamicSharedMemorySize, HSMEM_BYTES);
    cudaFuncSetAttribute(hgemm<false, false, true,  true >, cudaFuncAttributeMaxDynamicSharedMemorySize, HSMEM_BYTES);
    cudaFuncSetAttribute(hgemm<false, true,  false, false>, cudaFuncAttributeMaxDynamicSharedMemorySize, HSMEM_BYTES);

    // 0) all weights -> fp16 (single fused launch)
    cvt_all_k<<<CVT_N4 / 256, 256>>>(qkv_w, wq, proj_w, wp, w1, tw1, w2, tw2, w3, tw3);

    // 1) hh = LN1(x)
    layernorm_k<<<M_, 256>>>(x, ln1_g, ln1_b, hh);
    // 2) qkvh = hh @ qkv_w^T + qkv_b  (half out)
    hgemm<true, false, true, false><<<dim3(3*C_/128, M_/128), 256, HSMEM_BYTES>>>(
        hh, wq, qkv_b, nullptr, nullptr, qkvh, M_, 3*C_, C_);
    // 3) oh = causal_attention(qkvh)
    flash16_k<<<dim3(N_/FA_BR, B_*H_), 256>>>(qkvh, oh);
    // 4) x1 = x + oh @ proj_w^T + proj_b  (fp32 out)
    hgemm<true, true, false, false><<<dim3(C_/128, M_/128), 256, HSMEM_BYTES>>>(
        oh, wp, proj_b, x, nullptr, x1, M_, C_, C_);
    // 5) hh = LN2(x1)
    layernorm_k<<<M_, 256>>>(x1, ln2_g, ln2_b, hh);
    // 6) ah = hh @ w1^T  (half out)
    hgemm<false, false, true, false><<<dim3(FF_/128, M_/128), 256, HSMEM_BYTES>>>(
        hh, tw1, nullptr, nullptr, nullptr, ah, M_, FF_, C_);
    // 7) bh = silu(ah) * (hh @ w3^T)   (fused epilogue, half out)
    hgemm<false, false, true, true><<<dim3(FF_/128, M_/128), 256, HSMEM_BYTES>>>(
        hh, tw3, nullptr, nullptr, ah, bh, M_, FF_, C_);
    // 8) out = x1 + bh @ w2^T  (fp32 out)
    hgemm<false, true, false, false><<<dim3(C_/128, M_/128), 256, HSMEM_BYTES>>>(
        bh, tw2, nullptr, x1, nullptr, out, M_, C_, FF_);
}

// round 15
// speedup vs baseline: 1.0448x; 1.0124x over previous
#include <cuda_runtime.h>
#include <cuda_fp16.h>
#include <math.h>
#include <stdint.h>

#define B_ 4
#define N_ 2048
#define C_ 1024
#define H_ 16
#define D_ 64
#define FF_ 4096
#define M_ (B_ * N_)   // 8192 rows

// ---------------- scratch ----------------------------------------------------
__device__ float  g_x1 [M_ * C_];      // residual after attention (fp32)
__device__ __half g_hh [M_ * C_];      // LN output (half)
__device__ __half g_qkvh[M_ * 3 * C_]; // qkv projections (half)
__device__ __half g_oh [M_ * C_];      // attention output (half)
__device__ __half g_ah [M_ * FF_];     // h@w1^T (half)
__device__ __half g_bh [M_ * FF_];     // silu(ah) * (h@w3^T) (half)
// fp16 weights
__device__ __half g_wqh[3 * C_ * C_];
__device__ __half g_wph[C_ * C_];
__device__ __half g_w1h[FF_ * C_];
__device__ __half g_w2h[C_ * FF_];
__device__ __half g_w3h[FF_ * C_];

// ---------------- helpers ----------------------------------------------------
__device__ __forceinline__ uint32_t smem_u32(const void* p) {
    uint32_t a;
    asm("{ .reg .u64 t; cvta.to.shared.u64 t, %1; cvt.u32.u64 %0, t; }" : "=r"(a) : "l"(p));
    return a;
}
__device__ __forceinline__ uint32_t h2_u32(__half2 h) {
    return *reinterpret_cast<uint32_t*>(&h);
}
__device__ __forceinline__ __half2 u32_h2(uint32_t u) {
    return *reinterpret_cast<__half2*>(&u);
}
__device__ __forceinline__ float ex2f(float x) {
    float y;
    asm("ex2.approx.ftz.f32 %0, %1;" : "=f"(y) : "f"(x));
    return y;
}
#define CP_ASYNC16(dst, src) \
    asm volatile("cp.async.cg.shared.global [%0], [%1], 16;" :: "r"(dst), "l"(src))
#define CP_COMMIT() asm volatile("cp.async.commit_group;" ::: "memory")
#define CP_WAIT(n)  asm volatile("cp.async.wait_group %0;" :: "n"(n) : "memory")

#define LDM_X4(r0, r1, r2, r3, addr) \
    asm volatile("ldmatrix.sync.aligned.m8n8.x4.shared.b16 {%0,%1,%2,%3}, [%4];" \
                 : "=r"(r0), "=r"(r1), "=r"(r2), "=r"(r3) : "r"(addr))
#define LDM_X4_T(r0, r1, r2, r3, addr) \
    asm volatile("ldmatrix.sync.aligned.m8n8.x4.trans.shared.b16 {%0,%1,%2,%3}, [%4];" \
                 : "=r"(r0), "=r"(r1), "=r"(r2), "=r"(r3) : "r"(addr))

__device__ __forceinline__ void mma_f16(float* c, const uint32_t* a,
                                        uint32_t b0, uint32_t b1) {
    asm volatile(
        "mma.sync.aligned.m16n8k16.row.col.f32.f16.f16.f32 "
        "{%0,%1,%2,%3}, {%4,%5,%6,%7}, {%8,%9}, {%0,%1,%2,%3};"
        : "+f"(c[0]), "+f"(c[1]), "+f"(c[2]), "+f"(c[3])
        : "r"(a[0]), "r"(a[1]), "r"(a[2]), "r"(a[3]), "r"(b0), "r"(b1));
}

// ---------------- fused fp32 -> fp16 weight conversion -----------------------
#define CVT_N0 786432              // qkv_w  3M floats /4
#define CVT_N1 (CVT_N0 + 262144)   // proj_w
#define CVT_N2 (CVT_N1 + 1048576)  // w1
#define CVT_N3 (CVT_N2 + 1048576)  // w2
#define CVT_N4 (CVT_N3 + 1048576)  // w3

__global__ void __launch_bounds__(256) cvt_all_k(
    const float* __restrict__ s0, __half* __restrict__ d0,
    const float* __restrict__ s1, __half* __restrict__ d1,
    const float* __restrict__ s2, __half* __restrict__ d2,
    const float* __restrict__ s3, __half* __restrict__ d3,
    const float* __restrict__ s4, __half* __restrict__ d4)
{
    int i = blockIdx.x * 256 + threadIdx.x;
    const float* s; __half* d; int base;
    if      (i < CVT_N0) { s = s0; d = d0; base = 0; }
    else if (i < CVT_N1) { s = s1; d = d1; base = CVT_N0; }
    else if (i < CVT_N2) { s = s2; d = d2; base = CVT_N1; }
    else if (i < CVT_N3) { s = s3; d = d3; base = CVT_N2; }
    else                 { s = s4; d = d4; base = CVT_N3; }
    int j = i - base;
    float4 v = ((const float4*)s)[j];
    __half2* o = (__half2*)d + j * 2;
    o[0] = __floats2half2_rn(v.x, v.y);
    o[1] = __floats2half2_rn(v.z, v.w);
}

// ---------------- LayerNorm (half output) ------------------------------------
__global__ void __launch_bounds__(256) layernorm_k(
    const float* __restrict__ x, const float* __restrict__ gam,
    const float* __restrict__ bet, __half* __restrict__ out)
{
    int row = blockIdx.x;
    const float* xr = x + (size_t)row * C_;
    __half2* orow = (__half2*)(out + (size_t)row * C_);
    int t = threadIdx.x;

    float4 v = *(const float4*)(xr + t * 4);
    float s1 = v.x + v.y + v.z + v.w;
    float s2 = v.x*v.x + v.y*v.y + v.z*v.z + v.w*v.w;
    #pragma unroll
    for (int o = 16; o; o >>= 1) {
        s1 += __shfl_xor_sync(0xffffffffu, s1, o);
        s2 += __shfl_xor_sync(0xffffffffu, s2, o);
    }
    __shared__ float r1[8], r2[8];
    __shared__ float mu_s, rs_s;
    if ((t & 31) == 0) { r1[t >> 5] = s1; r2[t >> 5] = s2; }
    __syncthreads();
    if (t == 0) {
        float a = 0.f, b = 0.f;
        #pragma unroll
        for (int i = 0; i < 8; i++) { a += r1[i]; b += r2[i]; }
        float mu = a * (1.f / C_);
        float var = b * (1.f / C_) - mu * mu;
        mu_s = mu; rs_s = rsqrtf(var + 1e-6f);
    }
    __syncthreads();
    float mu = mu_s, rs = rs_s;
    float4 gv = *(const float4*)(gam + t * 4);
    float4 bv = *(const float4*)(bet + t * 4);
    float ox = (v.x - mu) * rs * gv.x + bv.x;
    float oy = (v.y - mu) * rs * gv.y + bv.y;
    float oz = (v.z - mu) * rs * gv.z + bv.z;
    float ow = (v.w - mu) * rs * gv.w + bv.w;
    orow[t * 2 + 0] = __floats2half2_rn(ox, oy);
    orow[t * 2 + 1] = __floats2half2_rn(oz, ow);
}

// ---------------- fp16 mma GEMM: C = A(MxK)*B(NxK)^T (+bias)(+res)(+silu) ----
// 128x128 tile, BK=32 halves, 4-stage cp.async, 256 threads, warp tile 64x32.
#define APITCH 80                      // bytes per smem row (64B data + 16B pad)
#define ATILE_B (128 * APITCH)         // 10240
#define STAGE_B (2 * ATILE_B)          // 20480
#define HSMEM_BYTES (4 * STAGE_B)      // 81920

template<bool BIAS, bool RES, bool HOUT, bool SILU>
__global__ void __launch_bounds__(256, 2) hgemm(
    const __half* __restrict__ A, const __half* __restrict__ Bm,
    const float* __restrict__ bias, const float* __restrict__ res,
    const __half* __restrict__ sa,
    void* __restrict__ Cc, int M, int Nn, int K)
{
    extern __shared__ char smc[];
    uint32_t sb = smem_u32(smc);
    const int tid = threadIdx.x;
    const int warp = tid >> 5, lane = tid & 31;
    const int m0 = blockIdx.y * 128, n0 = blockIdx.x * 128;
    const int wm = (warp >> 2) * 64, wn = (warp & 3) * 32;
    const int gr = lane >> 2, q = lane & 3;
    const int oct = lane >> 3, orow = lane & 7;

    const int lrow = tid >> 1;
    const int lc = (tid & 1) * 2;
    const __half* Ap = A  + (size_t)(m0 + lrow) * K + lc * 8;
    const __half* Bp = Bm + (size_t)(n0 + lrow) * K + lc * 8;
    const uint32_t woA = (uint32_t)lrow * APITCH + lc * 16;
    const uint32_t woB = woA + ATILE_B;

    float acc[4][4][4];
    #pragma unroll
    for (int i = 0; i < 4; i++)
        #pragma unroll
        for (int j = 0; j < 4; j++)
            #pragma unroll
            for (int c = 0; c < 4; c++) acc[i][j][c] = 0.f;

    const int NS = K >> 5;

    #pragma unroll
    for (int s = 0; s < 3; s++) {
        uint32_t st = sb + (uint32_t)s * STAGE_B;
        CP_ASYNC16(st + woA,      Ap + (size_t)s * 32);
        CP_ASYNC16(st + woA + 16, Ap + (size_t)s * 32 + 8);
        CP_ASYNC16(st + woB,      Bp + (size_t)s * 32);
        CP_ASYNC16(st + woB + 16, Bp + (size_t)s * 32 + 8);
        CP_COMMIT();
    }

    for (int s = 0; s < NS; s++) {
        CP_WAIT(2);
        __syncthreads();

        int ns = s + 3;
        if (ns < NS) {
            uint32_t st = sb + (uint32_t)(ns & 3) * STAGE_B;
            CP_ASYNC16(st + woA,      Ap + (size_t)ns * 32);
            CP_ASYNC16(st + woA + 16, Ap + (size_t)ns * 32 + 8);
            CP_ASYNC16(st + woB,      Bp + (size_t)ns * 32);
            CP_ASYNC16(st + woB + 16, Bp + (size_t)ns * 32 + 8);
            CP_COMMIT();
        } else {
            CP_COMMIT();
        }

        uint32_t ab = sb + (uint32_t)(s & 3) * STAGE_B;
        uint32_t bb = ab + ATILE_B;

        #pragma unroll
        for (int kk = 0; kk < 2; kk++) {
            uint32_t a[4][4], b[2][4];
            const int kc = kk * 2 + (oct >> 1);
            #pragma unroll
            for (int mi = 0; mi < 4; mi++) {
                int r = wm + mi * 16 + (oct & 1) * 8 + orow;
                LDM_X4(a[mi][0], a[mi][1], a[mi][2], a[mi][3],
                       ab + (uint32_t)r * APITCH + kc * 16);
            }
            #pragma unroll
            for (int nj = 0; nj < 2; nj++) {
                int r = wn + nj * 16 + (oct & 1) * 8 + orow;
                LDM_X4(b[nj][0], b[nj][1], b[nj][2], b[nj][3],
                       bb + (uint32_t)r * APITCH + kc * 16);
            }
            #pragma unroll
            for (int mi = 0; mi < 4; mi++) {
                #pragma unroll
                for (int nj = 0; nj < 2; nj++) {
                    mma_f16(acc[mi][nj * 2 + 0], a[mi], b[nj][0], b[nj][2]);
                    mma_f16(acc[mi][nj * 2 + 1], a[mi], b[nj][1], b[nj][3]);
                }
            }
        }
    }

    #pragma unroll
    for (int mi = 0; mi < 4; mi++) {
        int m = m0 + wm + mi * 16 + gr;
        #pragma unroll
        for (int ni = 0; ni < 4; ni++) {
            int n = n0 + wn + ni * 8 + 2 * q;
            float2 v0 = make_float2(acc[mi][ni][0], acc[mi][ni][1]);
            float2 v1 = make_float2(acc[mi][ni][2], acc[mi][ni][3]);
            if (BIAS) {
                float2 bv = *(const float2*)(bias + n);
                v0.x += bv.x; v0.y += bv.y;
                v1.x += bv.x; v1.y += bv.y;
            }
            if (RES) {
                float2 r0 = *(const float2*)(res + (size_t)m * Nn + n);
                float2 r1 = *(const float2*)(res + (size_t)(m + 8) * Nn + n);
                v0.x += r0.x; v0.y += r0.y;
                v1.x += r1.x; v1.y += r1.y;
            }
            if (SILU) {
                float2 a0 = __half22float2(*(const __half2*)(sa + (size_t)m * Nn + n));
                float2 a1 = __half22float2(*(const __half2*)(sa + (size_t)(m + 8) * Nn + n));
                v0.x *= a0.x / (1.f + __expf(-a0.x));
                v0.y *= a0.y / (1.f + __expf(-a0.y));
                v1.x *= a1.x / (1.f + __expf(-a1.x));
                v1.y *= a1.y / (1.f + __expf(-a1.y));
            }
            if (HOUT) {
                __half* Ch = (__half*)Cc;
                *(__half2*)(Ch + (size_t)m * Nn + n)       = __floats2half2_rn(v0.x, v0.y);
                *(__half2*)(Ch + (size_t)(m + 8) * Nn + n) = __floats2half2_rn(v1.x, v1.y);
            } else {
                float* Cf = (float*)Cc;
                *(float2*)(Cf + (size_t)m * Nn + n) = v0;
                *(float2*)(Cf + (size_t)(m + 8) * Nn + n) = v1;
            }
        }
    }
}

// ---------------- tensor-core causal flash attention --------------------------
// BR=128 (8 warps x 16 rows), BC=64. fp16 mma; softmax in log2 domain (ex2).
#define FA_BR 128
#define FA_BC 64
#define FA_PITCH 72                    // halves per smem row (144B)

__global__ void __launch_bounds__(256, 2) flash16_k(
    const __half* __restrict__ qkv, __half* __restrict__ O)
{
    __shared__ __half Qs[FA_BR * FA_PITCH];
    __shared__ __half Ks[2][FA_BC * FA_PITCH];
    __shared__ __half Vs[2][FA_BC * FA_PITCH];

    const int qt = (int)gridDim.x - 1 - (int)blockIdx.x;   // heavy tiles first
    const int bh = blockIdx.y;
    const int b = bh >> 4, h = bh & 15;
    const int tid = threadIdx.x, warp = tid >> 5, lane = tid & 31;
    const int gr = lane >> 2, q = lane & 3;
    const int wq = warp * 16;
    const int qr0 = qt * FA_BR;

    const uint32_t qb = smem_u32(Qs);
    const uint32_t kb2[2] = { smem_u32(Ks[0]), smem_u32(Ks[1]) };
    const uint32_t vb2[2] = { smem_u32(Vs[0]), smem_u32(Vs[1]) };

    const size_t rstride = 3 * C_;
    const __half* base0 = qkv + (size_t)(b * N_) * rstride;
    const int nkt = 2 * qt + 2;
    const float SCL = 0.125f * 1.44269504089f;   // 1/sqrt(D) * log2(e)

    // per-thread K/V cp.async geometry
    const int lr0 = tid >> 3, lcc = (tid & 7) * 8;
    const int lr1 = lr0 + 32;
    const uint32_t so0 = ((uint32_t)lr0 * FA_PITCH + lcc) * 2;
    const uint32_t so1 = ((uint32_t)lr1 * FA_PITCH + lcc) * 2;

    // hoisted per-thread ldmatrix offsets
    const int rk = lane & 15, hi16 = lane >> 4;
    uint32_t koff[4], voff[4];
    #pragma unroll
    for (int nj = 0; nj < 4; nj++)
        koff[nj] = (uint32_t)((nj * 16 + rk) * FA_PITCH) * 2 + hi16 * 16;
    #pragma unroll
    for (int kg = 0; kg < 4; kg++)
        voff[kg] = (uint32_t)((kg * 16 + rk) * FA_PITCH) * 2 + hi16 * 16;

    // prefetch tile 0 (K,V)
    {
        const __half* kbase = base0 + C_ + h * D_;
        CP_ASYNC16(kb2[0] + so0, kbase + (size_t)lr0 * rstride + lcc);
        CP_ASYNC16(kb2[0] + so1, kbase + (size_t)lr1 * rstride + lcc);
        CP_ASYNC16(vb2[0] + so0, kbase + (size_t)lr0 * rstride + C_ + lcc);
        CP_ASYNC16(vb2[0] + so1, kbase + (size_t)lr1 * rstride + C_ + lcc);
        CP_COMMIT();
    }

    // load Q tile
    const __half* qbase = base0 + h * D_;
    #pragma unroll
    for (int i = 0; i < 4; i++) {
        int idx = tid + i * 256;
        int r = idx >> 3, c = idx & 7;
        *(uint4*)(Qs + r * FA_PITCH + c * 8) =
            *(const uint4*)(qbase + (size_t)(qr0 + r) * rstride + c * 8);
    }
    __syncthreads();

    // preload Q A-fragments
    uint32_t qa[4][4];
    {
        int r = wq + rk;
        #pragma unroll
        for (int kc = 0; kc < 4; kc++) {
            LDM_X4(qa[kc][0], qa[kc][1], qa[kc][2], qa[kc][3],
                   qb + (uint32_t)(r * FA_PITCH) * 2 + (uint32_t)kc * 32 + hi16 * 16);
        }
    }

    float m0 = -INFINITY, m1 = -INFINITY, l0 = 0.f, l1 = 0.f;
    float o[8][4];
    #pragma unroll
    for (int i = 0; i < 8; i++)
        #pragma unroll
        for (int j = 0; j < 4; j++) o[i][j] = 0.f;

    const int row0 = qr0 + wq + gr;
    const int row1 = row0 + 8;

    for (int kt = 0; kt < nkt; kt++) {
        CP_WAIT(0);
        __syncthreads();

        int nb = kt + 1;
        if (nb < nkt) {
            const __half* kbase = base0 + (size_t)(nb * FA_BC) * rstride + C_ + h * D_;
            uint32_t kbn = kb2[nb & 1], vbn = vb2[nb & 1];
            CP_ASYNC16(kbn + so0, kbase + (size_t)lr0 * rstride + lcc);
            CP_ASYNC16(kbn + so1, kbase + (size_t)lr1 * rstride + lcc);
            CP_ASYNC16(vbn + so0, kbase + (size_t)lr0 * rstride + C_ + lcc);
            CP_ASYNC16(vbn + so1, kbase + (size_t)lr1 * rstride + C_ + lcc);
            CP_COMMIT();
        } else {
            CP_COMMIT();
        }

        const uint32_t kb = kb2[kt & 1];
        const uint32_t vb = vb2[kt & 1];

        // S = Q @ K^T
        float sc[8][4];
        #pragma unroll
        for (int i = 0; i < 8; i++)
            #pragma unroll
            for (int j = 0; j < 4; j++) sc[i][j] = 0.f;

        #pragma unroll
        for (int kc = 0; kc < 4; kc++) {
            #pragma unroll
            for (int nj = 0; nj < 4; nj++) {
                uint32_t b0, b1, b2, b3;
                LDM_X4(b0, b1, b2, b3, kb + koff[nj] + (uint32_t)kc * 32);
                mma_f16(sc[nj * 2 + 0], qa[kc], b0, b2);
                mma_f16(sc[nj * 2 + 1], qa[kc], b1, b3);
            }
        }

        // scale (log2 domain) + causal mask + row max
        const bool need_mask = (kt * FA_BC + FA_BC - 1) > (qr0 + wq);
        float mt0 = -INFINITY, mt1 = -INFINITY;
        #pragma unroll
        for (int nt = 0; nt < 8; nt++) {
            int key = kt * FA_BC + nt * 8 + 2 * q;
            #pragma unroll
            for (int j = 0; j < 4; j++) {
                float s = sc[nt][j] * SCL;
                if (need_mask) {
                    int k_ = key + (j & 1);
                    int r_ = (j < 2) ? row0 : row1;
                    if (k_ > r_) s = -INFINITY;
                }
                sc[nt][j] = s;
            }
            mt0 = fmaxf(mt0, fmaxf(sc[nt][0], sc[nt][1]));
            mt1 = fmaxf(mt1, fmaxf(sc[nt][2], sc[nt][3]));
        }
        mt0 = fmaxf(mt0, __shfl_xor_sync(0xffffffffu, mt0, 1));
        mt0 = fmaxf(mt0, __shfl_xor_sync(0xffffffffu, mt0, 2));
        mt1 = fmaxf(mt1, __shfl_xor_sync(0xffffffffu, mt1, 1));
        mt1 = fmaxf(mt1, __shfl_xor_sync(0xffffffffu, mt1, 2));

        float nm0 = fmaxf(m0, mt0), nm1 = fmaxf(m1, mt1);
        if (nm0 > m0) {                 // rescale only when max advanced
            float corr0 = ex2f(m0 - nm0);
            #pragma unroll
            for (int nt = 0; nt < 8; nt++) { o[nt][0] *= corr0; o[nt][1] *= corr0; }
            l0 *= corr0;
            m0 = nm0;
        }
        if (nm1 > m1) {
            float corr1 = ex2f(m1 - nm1);
            #pragma unroll
            for (int nt = 0; nt < 8; nt++) { o[nt][2] *= corr1; o[nt][3] *= corr1; }
            l1 *= corr1;
            m1 = nm1;
        }

        // per-16-key group: exponentiate (ex2), pack P, P @ V
        #pragma unroll
        for (int kg = 0; kg < 4; kg++) {
            float p00 = ex2f(sc[2*kg][0]   - m0), p01 = ex2f(sc[2*kg][1]   - m0);
            float p10 = ex2f(sc[2*kg][2]   - m1), p11 = ex2f(sc[2*kg][3]   - m1);
            float p20 = ex2f(sc[2*kg+1][0] - m0), p21 = ex2f(sc[2*kg+1][1] - m0);
            float p30 = ex2f(sc[2*kg+1][2] - m1), p31 = ex2f(sc[2*kg+1][3] - m1);
            l0 += p00 + p01 + p20 + p21;
            l1 += p10 + p11 + p30 + p31;
            uint32_t P[4];
            P[0] = h2_u32(__floats2half2_rn(p00, p01));
            P[1] = h2_u32(__floats2half2_rn(p10, p11));
            P[2] = h2_u32(__floats2half2_rn(p20, p21));
            P[3] = h2_u32(__floats2half2_rn(p30, p31));
            #pragma unroll
            for (int dj = 0; dj < 4; dj++) {
                uint32_t v0, v1, v2, v3;
                LDM_X4_T(v0, v1, v2, v3, vb + voff[kg] + (uint32_t)dj * 32);
                mma_f16(o[dj * 2 + 0], P, v0, v1);
                mma_f16(o[dj * 2 + 1], P, v2, v3);
            }
        }
    }

    // l is a row quantity — sum partials across the quad.
    l0 += __shfl_xor_sync(0xffffffffu, l0, 1);
    l0 += __shfl_xor_sync(0xffffffffu, l0, 2);
    l1 += __shfl_xor_sync(0xffffffffu, l1, 1);
    l1 += __shfl_xor_sync(0xffffffffu, l1, 2);

    float inv0 = 1.f / l0, inv1 = 1.f / l1;
    __half* ob = O + (size_t)(b * N_) * C_ + h * D_;
    #pragma unroll
    for (int nt = 0; nt < 8; nt++) {
        int d = nt * 8 + 2 * q;
        *(__half2*)(ob + (size_t)row0 * C_ + d) =
            __floats2half2_rn(o[nt][0] * inv0, o[nt][1] * inv0);
        *(__half2*)(ob + (size_t)row1 * C_ + d) =
            __floats2half2_rn(o[nt][2] * inv1, o[nt][3] * inv1);
    }
}

// ---------------- launcher ---------------------------------------------------
extern "C" void kernel_launch(void* const* d_in, const int* in_sizes, int n_in,
                              void* d_out, int out_size)
{
    const float* x      = (const float*)d_in[0];
    const float* qkv_w  = (const float*)d_in[2];
    const float* qkv_b  = (const float*)d_in[3];
    const float* proj_w = (const float*)d_in[4];
    const float* proj_b = (const float*)d_in[5];
    const float* ln1_g  = (const float*)d_in[6];
    const float* ln1_b  = (const float*)d_in[7];
    const float* ln2_g  = (const float*)d_in[8];
    const float* ln2_b  = (const float*)d_in[9];
    const float* w1     = (const float*)d_in[10];
    const float* w2     = (const float*)d_in[11];
    const float* w3     = (const float*)d_in[12];
    float* out = (float*)d_out;

    float *x1;
    __half *hh, *qkvh, *oh, *ah, *bh, *wq, *wp, *tw1, *tw2, *tw3;
    cudaGetSymbolAddress((void**)&x1,   g_x1);
    cudaGetSymbolAddress((void**)&hh,   g_hh);
    cudaGetSymbolAddress((void**)&qkvh, g_qkvh);
    cudaGetSymbolAddress((void**)&oh,   g_oh);
    cudaGetSymbolAddress((void**)&ah,   g_ah);
    cudaGetSymbolAddress((void**)&bh,   g_bh);
    cudaGetSymbolAddress((void**)&wq,   g_wqh);
    cudaGetSymbolAddress((void**)&wp,   g_wph);
    cudaGetSymbolAddress((void**)&tw1,  g_w1h);
    cudaGetSymbolAddress((void**)&tw2,  g_w2h);
    cudaGetSymbolAddress((void**)&tw3,  g_w3h);

    cudaFuncSetAttribute(hgemm<true,  false, true,  false>, cudaFuncAttributeMaxDynamicSharedMemorySize, HSMEM_BYTES);
    cudaFuncSetAttribute(hgemm<true,  true,  false, false>, cudaFuncAttributeMaxDynamicSharedMemorySize, HSMEM_BYTES);
    cudaFuncSetAttribute(hgemm<false, false, true,  false>, cudaFuncAttributeMaxDynamicSharedMemorySize, HSMEM_BYTES);
    cudaFuncSetAttribute(hgemm<false, false, true,  true >, cudaFuncAttributeMaxDynamicSharedMemorySize, HSMEM_BYTES);
    cudaFuncSetAttribute(hgemm<false, true,  false, false>, cudaFuncAttributeMaxDynamicSharedMemorySize, HSMEM_BYTES);

    // 0) all weights -> fp16 (single fused launch)
    cvt_all_k<<<CVT_N4 / 256, 256>>>(qkv_w, wq, proj_w, wp, w1, tw1, w2, tw2, w3, tw3);

    // 1) hh = LN1(x)
    layernorm_k<<<M_, 256>>>(x, ln1_g, ln1_b, hh);
    // 2) qkvh = hh @ qkv_w^T + qkv_b  (half out)
    hgemm<true, false, true, false><<<dim3(3*C_/128, M_/128), 256, HSMEM_BYTES>>>(
        hh, wq, qkv_b, nullptr, nullptr, qkvh, M_, 3*C_, C_);
    // 3) oh = causal_attention(qkvh)
    flash16_k<<<dim3(N_/FA_BR, B_*H_), 256>>>(qkvh, oh);
    // 4) x1 = x + oh @ proj_w^T + proj_b  (fp32 out)
    hgemm<true, true, false, false><<<dim3(C_/128, M_/128), 256, HSMEM_BYTES>>>(
        oh, wp, proj_b, x, nullptr, x1, M_, C_, C_);
    // 5) hh = LN2(x1)
    layernorm_k<<<M_, 256>>>(x1, ln2_g, ln2_b, hh);
    // 6) ah = hh @ w1^T  (half out)
    hgemm<false, false, true, false><<<dim3(FF_/128, M_/128), 256, HSMEM_BYTES>>>(
        hh, tw1, nullptr, nullptr, nullptr, ah, M_, FF_, C_);
    // 7) bh = silu(ah) * (hh @ w3^T)   (fused epilogue, half out)
    hgemm<false, false, true, true><<<dim3(FF_/128, M_/128), 256, HSMEM_BYTES>>>(
        hh, tw3, nullptr, nullptr, ah, bh, M_, FF_, C_);
    // 8) out = x1 + bh @ w2^T  (fp32 out)
    hgemm<false, true, false, false><<<dim3(C_/128, M_/128), 256, HSMEM_BYTES>>>(
        bh, tw2, nullptr, x1, nullptr, out, M_, C_, FF_);
}

// round 16
// speedup vs baseline: 1.0470x; 1.0021x over previous
#include <cuda_runtime.h>
#include <cuda_fp16.h>
#include <math.h>
#include <stdint.h>

#define B_ 4
#define N_ 2048
#define C_ 1024
#define H_ 16
#define D_ 64
#define FF_ 4096
#define M_ (B_ * N_)   // 8192 rows

// ---------------- scratch ----------------------------------------------------
__device__ float  g_x1 [M_ * C_];      // residual after attention (fp32)
__device__ __half g_hh [M_ * C_];      // LN output (half)
__device__ __half g_qkvh[M_ * 3 * C_]; // qkv projections (half)
__device__ __half g_oh [M_ * C_];      // attention output (half)
__device__ __half g_ah [M_ * FF_];     // h@w1^T (half)
__device__ __half g_bh [M_ * FF_];     // silu(ah) * (h@w3^T) (half)
// fp16 weights
__device__ __half g_wqh[3 * C_ * C_];
__device__ __half g_wph[C_ * C_];
__device__ __half g_w1h[FF_ * C_];
__device__ __half g_w2h[C_ * FF_];
__device__ __half g_w3h[FF_ * C_];

// ---------------- helpers ----------------------------------------------------
__device__ __forceinline__ uint32_t smem_u32(const void* p) {
    uint32_t a;
    asm("{ .reg .u64 t; cvta.to.shared.u64 t, %1; cvt.u32.u64 %0, t; }" : "=r"(a) : "l"(p));
    return a;
}
__device__ __forceinline__ uint32_t h2_u32(__half2 h) {
    return *reinterpret_cast<uint32_t*>(&h);
}
__device__ __forceinline__ __half2 u32_h2(uint32_t u) {
    return *reinterpret_cast<__half2*>(&u);
}
__device__ __forceinline__ float ex2f(float x) {
    float y;
    asm("ex2.approx.ftz.f32 %0, %1;" : "=f"(y) : "f"(x));
    return y;
}
__device__ __forceinline__ uint32_t h2ex2(uint32_t x) {
    uint32_t y;
    asm("ex2.approx.f16x2 %0, %1;" : "=r"(y) : "r"(x));
    return y;
}
#define CP_ASYNC16(dst, src) \
    asm volatile("cp.async.cg.shared.global [%0], [%1], 16;" :: "r"(dst), "l"(src))
#define CP_COMMIT() asm volatile("cp.async.commit_group;" ::: "memory")
#define CP_WAIT(n)  asm volatile("cp.async.wait_group %0;" :: "n"(n) : "memory")

#define LDM_X4(r0, r1, r2, r3, addr) \
    asm volatile("ldmatrix.sync.aligned.m8n8.x4.shared.b16 {%0,%1,%2,%3}, [%4];" \
                 : "=r"(r0), "=r"(r1), "=r"(r2), "=r"(r3) : "r"(addr))
#define LDM_X4_T(r0, r1, r2, r3, addr) \
    asm volatile("ldmatrix.sync.aligned.m8n8.x4.trans.shared.b16 {%0,%1,%2,%3}, [%4];" \
                 : "=r"(r0), "=r"(r1), "=r"(r2), "=r"(r3) : "r"(addr))
#define LDM_X2_T(r0, r1, addr) \
    asm volatile("ldmatrix.sync.aligned.m8n8.x2.trans.shared.b16 {%0,%1}, [%2];" \
                 : "=r"(r0), "=r"(r1) : "r"(addr))

__device__ __forceinline__ void mma_f16(float* c, const uint32_t* a,
                                        uint32_t b0, uint32_t b1) {
    asm volatile(
        "mma.sync.aligned.m16n8k16.row.col.f32.f16.f16.f32 "
        "{%0,%1,%2,%3}, {%4,%5,%6,%7}, {%8,%9}, {%0,%1,%2,%3};"
        : "+f"(c[0]), "+f"(c[1]), "+f"(c[2]), "+f"(c[3])
        : "r"(a[0]), "r"(a[1]), "r"(a[2]), "r"(a[3]), "r"(b0), "r"(b1));
}

// ---------------- fused fp32 -> fp16 weight conversion -----------------------
#define CVT_N0 786432
#define CVT_N1 (CVT_N0 + 262144)
#define CVT_N2 (CVT_N1 + 1048576)
#define CVT_N3 (CVT_N2 + 1048576)
#define CVT_N4 (CVT_N3 + 1048576)

__global__ void __launch_bounds__(256) cvt_all_k(
    const float* __restrict__ s0, __half* __restrict__ d0,
    const float* __restrict__ s1, __half* __restrict__ d1,
    const float* __restrict__ s2, __half* __restrict__ d2,
    const float* __restrict__ s3, __half* __restrict__ d3,
    const float* __restrict__ s4, __half* __restrict__ d4)
{
    int i = blockIdx.x * 256 + threadIdx.x;
    const float* s; __half* d; int base;
    if      (i < CVT_N0) { s = s0; d = d0; base = 0; }
    else if (i < CVT_N1) { s = s1; d = d1; base = CVT_N0; }
    else if (i < CVT_N2) { s = s2; d = d2; base = CVT_N1; }
    else if (i < CVT_N3) { s = s3; d = d3; base = CVT_N2; }
    else                 { s = s4; d = d4; base = CVT_N3; }
    int j = i - base;
    float4 v = ((const float4*)s)[j];
    __half2* o = (__half2*)d + j * 2;
    o[0] = __floats2half2_rn(v.x, v.y);
    o[1] = __floats2half2_rn(v.z, v.w);
}

// ---------------- LayerNorm (half output) ------------------------------------
__global__ void __launch_bounds__(256) layernorm_k(
    const float* __restrict__ x, const float* __restrict__ gam,
    const float* __restrict__ bet, __half* __restrict__ out)
{
    int row = blockIdx.x;
    const float* xr = x + (size_t)row * C_;
    __half2* orow = (__half2*)(out + (size_t)row * C_);
    int t = threadIdx.x;

    float4 v = *(const float4*)(xr + t * 4);
    float s1 = v.x + v.y + v.z + v.w;
    float s2 = v.x*v.x + v.y*v.y + v.z*v.z + v.w*v.w;
    #pragma unroll
    for (int o = 16; o; o >>= 1) {
        s1 += __shfl_xor_sync(0xffffffffu, s1, o);
        s2 += __shfl_xor_sync(0xffffffffu, s2, o);
    }
    __shared__ float r1[8], r2[8];
    __shared__ float mu_s, rs_s;
    if ((t & 31) == 0) { r1[t >> 5] = s1; r2[t >> 5] = s2; }
    __syncthreads();
    if (t == 0) {
        float a = 0.f, b = 0.f;
        #pragma unroll
        for (int i = 0; i < 8; i++) { a += r1[i]; b += r2[i]; }
        float mu = a * (1.f / C_);
        float var = b * (1.f / C_) - mu * mu;
        mu_s = mu; rs_s = rsqrtf(var + 1e-6f);
    }
    __syncthreads();
    float mu = mu_s, rs = rs_s;
    float4 gv = *(const float4*)(gam + t * 4);
    float4 bv = *(const float4*)(bet + t * 4);
    float ox = (v.x - mu) * rs * gv.x + bv.x;
    float oy = (v.y - mu) * rs * gv.y + bv.y;
    float oz = (v.z - mu) * rs * gv.z + bv.z;
    float ow = (v.w - mu) * rs * gv.w + bv.w;
    orow[t * 2 + 0] = __floats2half2_rn(ox, oy);
    orow[t * 2 + 1] = __floats2half2_rn(oz, ow);
}

// ---------------- fp16 mma GEMM: C = A(MxK)*B(NxK)^T (+bias)(+res)(+silu) ----
#define APITCH 80
#define ATILE_B (128 * APITCH)
#define STAGE_B (2 * ATILE_B)
#define HSMEM_BYTES (4 * STAGE_B)

template<bool BIAS, bool RES, bool HOUT, bool SILU>
__global__ void __launch_bounds__(256, 2) hgemm(
    const __half* __restrict__ A, const __half* __restrict__ Bm,
    const float* __restrict__ bias, const float* __restrict__ res,
    const __half* __restrict__ sa,
    void* __restrict__ Cc, int M, int Nn, int K)
{
    extern __shared__ char smc[];
    uint32_t sb = smem_u32(smc);
    const int tid = threadIdx.x;
    const int warp = tid >> 5, lane = tid & 31;
    const int m0 = blockIdx.y * 128, n0 = blockIdx.x * 128;
    const int wm = (warp >> 2) * 64, wn = (warp & 3) * 32;
    const int gr = lane >> 2, q = lane & 3;
    const int oct = lane >> 3, orow = lane & 7;

    const int lrow = tid >> 1;
    const int lc = (tid & 1) * 2;
    const __half* Ap = A  + (size_t)(m0 + lrow) * K + lc * 8;
    const __half* Bp = Bm + (size_t)(n0 + lrow) * K + lc * 8;
    const uint32_t woA = (uint32_t)lrow * APITCH + lc * 16;
    const uint32_t woB = woA + ATILE_B;

    float acc[4][4][4];
    #pragma unroll
    for (int i = 0; i < 4; i++)
        #pragma unroll
        for (int j = 0; j < 4; j++)
            #pragma unroll
            for (int c = 0; c < 4; c++) acc[i][j][c] = 0.f;

    const int NS = K >> 5;

    #pragma unroll
    for (int s = 0; s < 3; s++) {
        uint32_t st = sb + (uint32_t)s * STAGE_B;
        CP_ASYNC16(st + woA,      Ap + (size_t)s * 32);
        CP_ASYNC16(st + woA + 16, Ap + (size_t)s * 32 + 8);
        CP_ASYNC16(st + woB,      Bp + (size_t)s * 32);
        CP_ASYNC16(st + woB + 16, Bp + (size_t)s * 32 + 8);
        CP_COMMIT();
    }

    for (int s = 0; s < NS; s++) {
        CP_WAIT(2);
        __syncthreads();

        int ns = s + 3;
        if (ns < NS) {
            uint32_t st = sb + (uint32_t)(ns & 3) * STAGE_B;
            CP_ASYNC16(st + woA,      Ap + (size_t)ns * 32);
            CP_ASYNC16(st + woA + 16, Ap + (size_t)ns * 32 + 8);
            CP_ASYNC16(st + woB,      Bp + (size_t)ns * 32);
            CP_ASYNC16(st + woB + 16, Bp + (size_t)ns * 32 + 8);
            CP_COMMIT();
        } else {
            CP_COMMIT();
        }

        uint32_t ab = sb + (uint32_t)(s & 3) * STAGE_B;
        uint32_t bb = ab + ATILE_B;

        #pragma unroll
        for (int kk = 0; kk < 2; kk++) {
            uint32_t a[4][4], b[2][4];
            const int kc = kk * 2 + (oct >> 1);
            #pragma unroll
            for (int mi = 0; mi < 4; mi++) {
                int r = wm + mi * 16 + (oct & 1) * 8 + orow;
                LDM_X4(a[mi][0], a[mi][1], a[mi][2], a[mi][3],
                       ab + (uint32_t)r * APITCH + kc * 16);
            }
            #pragma unroll
            for (int nj = 0; nj < 2; nj++) {
                int r = wn + nj * 16 + (oct & 1) * 8 + orow;
                LDM_X4(b[nj][0], b[nj][1], b[nj][2], b[nj][3],
                       bb + (uint32_t)r * APITCH + kc * 16);
            }
            #pragma unroll
            for (int mi = 0; mi < 4; mi++) {
                #pragma unroll
                for (int nj = 0; nj < 2; nj++) {
                    mma_f16(acc[mi][nj * 2 + 0], a[mi], b[nj][0], b[nj][2]);
                    mma_f16(acc[mi][nj * 2 + 1], a[mi], b[nj][1], b[nj][3]);
                }
            }
        }
    }

    #pragma unroll
    for (int mi = 0; mi < 4; mi++) {
        int m = m0 + wm + mi * 16 + gr;
        #pragma unroll
        for (int ni = 0; ni < 4; ni++) {
            int n = n0 + wn + ni * 8 + 2 * q;
            float2 v0 = make_float2(acc[mi][ni][0], acc[mi][ni][1]);
            float2 v1 = make_float2(acc[mi][ni][2], acc[mi][ni][3]);
            if (BIAS) {
                float2 bv = *(const float2*)(bias + n);
                v0.x += bv.x; v0.y += bv.y;
                v1.x += bv.x; v1.y += bv.y;
            }
            if (RES) {
                float2 r0 = *(const float2*)(res + (size_t)m * Nn + n);
                float2 r1 = *(const float2*)(res + (size_t)(m + 8) * Nn + n);
                v0.x += r0.x; v0.y += r0.y;
                v1.x += r1.x; v1.y += r1.y;
            }
            if (SILU) {
                float2 a0 = __half22float2(*(const __half2*)(sa + (size_t)m * Nn + n));
                float2 a1 = __half22float2(*(const __half2*)(sa + (size_t)(m + 8) * Nn + n));
                v0.x *= a0.x / (1.f + __expf(-a0.x));
                v0.y *= a0.y / (1.f + __expf(-a0.y));
                v1.x *= a1.x / (1.f + __expf(-a1.x));
                v1.y *= a1.y / (1.f + __expf(-a1.y));
            }
            if (HOUT) {
                __half* Ch = (__half*)Cc;
                *(__half2*)(Ch + (size_t)m * Nn + n)       = __floats2half2_rn(v0.x, v0.y);
                *(__half2*)(Ch + (size_t)(m + 8) * Nn + n) = __floats2half2_rn(v1.x, v1.y);
            } else {
                float* Cf = (float*)Cc;
                *(float2*)(Cf + (size_t)m * Nn + n) = v0;
                *(float2*)(Cf + (size_t)(m + 8) * Nn + n) = v1;
            }
        }
    }
}

// ---------------- tensor-core causal flash attention --------------------------
// BR=128 (8 warps x 16 rows), BC=64. fp16 mma; softmax in log2 domain.
// p computed with ex2.approx.f16x2; l accumulated by mma against a ones-column
// stored in V's pad columns (64..71).
#define FA_BR 128
#define FA_BC 64
#define FA_PITCH 72                    // halves per smem row (144B)

__global__ void __launch_bounds__(256, 2) flash16_k(
    const __half* __restrict__ qkv, __half* __restrict__ O)
{
    __shared__ __half Qs[FA_BR * FA_PITCH];
    __shared__ __half Ks[2][FA_BC * FA_PITCH];
    __shared__ __half Vs[2][FA_BC * FA_PITCH];

    const int qt = (int)gridDim.x - 1 - (int)blockIdx.x;   // heavy tiles first
    const int bh = blockIdx.y;
    const int b = bh >> 4, h = bh & 15;
    const int tid = threadIdx.x, warp = tid >> 5, lane = tid & 31;
    const int gr = lane >> 2, q = lane & 3;
    const int wq = warp * 16;
    const int qr0 = qt * FA_BR;

    const uint32_t qb = smem_u32(Qs);
    const uint32_t kb2[2] = { smem_u32(Ks[0]), smem_u32(Ks[1]) };
    const uint32_t vb2[2] = { smem_u32(Vs[0]), smem_u32(Vs[1]) };

    const size_t rstride = 3 * C_;
    const __half* base0 = qkv + (size_t)(b * N_) * rstride;
    const int nkt = 2 * qt + 2;
    const float SCL = 0.125f * 1.44269504089f;   // 1/sqrt(D) * log2(e)

    // per-thread K/V cp.async geometry
    const int lr0 = tid >> 3, lcc = (tid & 7) * 8;
    const int lr1 = lr0 + 32;
    const uint32_t so0 = ((uint32_t)lr0 * FA_PITCH + lcc) * 2;
    const uint32_t so1 = ((uint32_t)lr1 * FA_PITCH + lcc) * 2;

    // hoisted per-thread ldmatrix offsets
    const int rk = lane & 15, hi16 = lane >> 4;
    uint32_t koff[4], voff[4], loff[4];
    #pragma unroll
    for (int nj = 0; nj < 4; nj++)
        koff[nj] = (uint32_t)((nj * 16 + rk) * FA_PITCH) * 2 + hi16 * 16;
    #pragma unroll
    for (int kg = 0; kg < 4; kg++) {
        voff[kg] = (uint32_t)((kg * 16 + rk) * FA_PITCH) * 2 + hi16 * 16;
        loff[kg] = (uint32_t)((kg * 16 + rk) * FA_PITCH) * 2 + 128;  // cols 64..71
    }

    // V pad columns 64..71: [1,0,0,0,0,0,0,0] in both buffers (cp.async writes
    // only bytes 0..127 of each row, so these persist for the whole kernel)
    if (tid < 128) {
        int buf = tid >> 6, r = tid & 63;
        __half* p = &Vs[buf][r * FA_PITCH + 64];
        *(uint4*)p = make_uint4(0x00003c00u, 0u, 0u, 0u);  // 1.0h, then zeros
    }

    // prefetch tile 0 (K,V)
    {
        const __half* kbase = base0 + C_ + h * D_;
        CP_ASYNC16(kb2[0] + so0, kbase + (size_t)lr0 * rstride + lcc);
        CP_ASYNC16(kb2[0] + so1, kbase + (size_t)lr1 * rstride + lcc);
        CP_ASYNC16(vb2[0] + so0, kbase + (size_t)lr0 * rstride + C_ + lcc);
        CP_ASYNC16(vb2[0] + so1, kbase + (size_t)lr1 * rstride + C_ + lcc);
        CP_COMMIT();
    }

    // load Q tile
    const __half* qbase = base0 + h * D_;
    #pragma unroll
    for (int i = 0; i < 4; i++) {
        int idx = tid + i * 256;
        int r = idx >> 3, c = idx & 7;
        *(uint4*)(Qs + r * FA_PITCH + c * 8) =
            *(const uint4*)(qbase + (size_t)(qr0 + r) * rstride + c * 8);
    }
    __syncthreads();

    // preload Q A-fragments
    uint32_t qa[4][4];
    {
        int r = wq + rk;
        #pragma unroll
        for (int kc = 0; kc < 4; kc++) {
            LDM_X4(qa[kc][0], qa[kc][1], qa[kc][2], qa[kc][3],
                   qb + (uint32_t)(r * FA_PITCH) * 2 + (uint32_t)kc * 32 + hi16 * 16);
        }
    }

    float m0 = -INFINITY, m1 = -INFINITY;
    float lacc[4] = {0.f, 0.f, 0.f, 0.f};    // l via mma: [0]=row0, [2]=row1 (q==0)
    float o[8][4];
    #pragma unroll
    for (int i = 0; i < 8; i++)
        #pragma unroll
        for (int j = 0; j < 4; j++) o[i][j] = 0.f;

    const int row0 = qr0 + wq + gr;
    const int row1 = row0 + 8;

    for (int kt = 0; kt < nkt; kt++) {
        CP_WAIT(0);
        __syncthreads();

        int nb = kt + 1;
        if (nb < nkt) {
            const __half* kbase = base0 + (size_t)(nb * FA_BC) * rstride + C_ + h * D_;
            uint32_t kbn = kb2[nb & 1], vbn = vb2[nb & 1];
            CP_ASYNC16(kbn + so0, kbase + (size_t)lr0 * rstride + lcc);
            CP_ASYNC16(kbn + so1, kbase + (size_t)lr1 * rstride + lcc);
            CP_ASYNC16(vbn + so0, kbase + (size_t)lr0 * rstride + C_ + lcc);
            CP_ASYNC16(vbn + so1, kbase + (size_t)lr1 * rstride + C_ + lcc);
            CP_COMMIT();
        } else {
            CP_COMMIT();
        }

        // whole key tile above the diagonal for this warp's rows? skip compute.
        if (kt * FA_BC > qr0 + wq + 15) continue;

        const uint32_t kb = kb2[kt & 1];
        const uint32_t vb = vb2[kt & 1];

        // S = Q @ K^T
        float sc[8][4];
        #pragma unroll
        for (int i = 0; i < 8; i++)
            #pragma unroll
            for (int j = 0; j < 4; j++) sc[i][j] = 0.f;

        #pragma unroll
        for (int kc = 0; kc < 4; kc++) {
            #pragma unroll
            for (int nj = 0; nj < 4; nj++) {
                uint32_t b0, b1, b2, b3;
                LDM_X4(b0, b1, b2, b3, kb + koff[nj] + (uint32_t)kc * 32);
                mma_f16(sc[nj * 2 + 0], qa[kc], b0, b2);
                mma_f16(sc[nj * 2 + 1], qa[kc], b1, b3);
            }
        }

        // scale (log2 domain) + causal mask + row max
        const bool need_mask = (kt * FA_BC + FA_BC - 1) > (qr0 + wq);
        float mt0 = -INFINITY, mt1 = -INFINITY;
        #pragma unroll
        for (int nt = 0; nt < 8; nt++) {
            int key = kt * FA_BC + nt * 8 + 2 * q;
            #pragma unroll
            for (int j = 0; j < 4; j++) {
                float s = sc[nt][j] * SCL;
                if (need_mask) {
                    int k_ = key + (j & 1);
                    int r_ = (j < 2) ? row0 : row1;
                    if (k_ > r_) s = -INFINITY;
                }
                sc[nt][j] = s;
            }
            mt0 = fmaxf(mt0, fmaxf(sc[nt][0], sc[nt][1]));
            mt1 = fmaxf(mt1, fmaxf(sc[nt][2], sc[nt][3]));
        }
        mt0 = fmaxf(mt0, __shfl_xor_sync(0xffffffffu, mt0, 1));
        mt0 = fmaxf(mt0, __shfl_xor_sync(0xffffffffu, mt0, 2));
        mt1 = fmaxf(mt1, __shfl_xor_sync(0xffffffffu, mt1, 1));
        mt1 = fmaxf(mt1, __shfl_xor_sync(0xffffffffu, mt1, 2));

        float nm0 = fmaxf(m0, mt0), nm1 = fmaxf(m1, mt1);
        if (nm0 > m0) {
            float corr0 = ex2f(m0 - nm0);
            #pragma unroll
            for (int nt = 0; nt < 8; nt++) { o[nt][0] *= corr0; o[nt][1] *= corr0; }
            lacc[0] *= corr0; lacc[1] *= corr0;
            m0 = nm0;
        }
        if (nm1 > m1) {
            float corr1 = ex2f(m1 - nm1);
            #pragma unroll
            for (int nt = 0; nt < 8; nt++) { o[nt][2] *= corr1; o[nt][3] *= corr1; }
            lacc[2] *= corr1; lacc[3] *= corr1;
            m1 = nm1;
        }

        // per-16-key group: p = ex2 in f16x2; l via mma against ones-column
        #pragma unroll
        for (int kg = 0; kg < 4; kg++) {
            uint32_t P[4];
            P[0] = h2ex2(h2_u32(__floats2half2_rn(sc[2*kg][0]   - m0, sc[2*kg][1]   - m0)));
            P[1] = h2ex2(h2_u32(__floats2half2_rn(sc[2*kg][2]   - m1, sc[2*kg][3]   - m1)));
            P[2] = h2ex2(h2_u32(__floats2half2_rn(sc[2*kg+1][0] - m0, sc[2*kg+1][1] - m0)));
            P[3] = h2ex2(h2_u32(__floats2half2_rn(sc[2*kg+1][2] - m1, sc[2*kg+1][3] - m1)));
            uint32_t lv0, lv1;
            LDM_X2_T(lv0, lv1, vb + loff[kg]);
            mma_f16(lacc, P, lv0, lv1);
            #pragma unroll
            for (int dj = 0; dj < 4; dj++) {
                uint32_t v0, v1, v2, v3;
                LDM_X4_T(v0, v1, v2, v3, vb + voff[kg] + (uint32_t)dj * 32);
                mma_f16(o[dj * 2 + 0], P, v0, v1);
                mma_f16(o[dj * 2 + 1], P, v2, v3);
            }
        }
    }

    // l lives in the q==0 lane of each quad (col 64): broadcast across the quad.
    float l0 = __shfl_sync(0xffffffffu, lacc[0], lane & ~3);
    float l1 = __shfl_sync(0xffffffffu, lacc[2], lane & ~3);

    float inv0 = 1.f / l0, inv1 = 1.f / l1;
    __half* ob = O + (size_t)(b * N_) * C_ + h * D_;
    #pragma unroll
    for (int nt = 0; nt < 8; nt++) {
        int d = nt * 8 + 2 * q;
        *(__half2*)(ob + (size_t)row0 * C_ + d) =
            __floats2half2_rn(o[nt][0] * inv0, o[nt][1] * inv0);
        *(__half2*)(ob + (size_t)row1 * C_ + d) =
            __floats2half2_rn(o[nt][2] * inv1, o[nt][3] * inv1);
    }
}

// ---------------- launcher ---------------------------------------------------
extern "C" void kernel_launch(void* const* d_in, const int* in_sizes, int n_in,
                              void* d_out, int out_size)
{
    const float* x      = (const float*)d_in[0];
    const float* qkv_w  = (const float*)d_in[2];
    const float* qkv_b  = (const float*)d_in[3];
    const float* proj_w = (const float*)d_in[4];
    const float* proj_b = (const float*)d_in[5];
    const float* ln1_g  = (const float*)d_in[6];
    const float* ln1_b  = (const float*)d_in[7];
    const float* ln2_g  = (const float*)d_in[8];
    const float* ln2_b  = (const float*)d_in[9];
    const float* w1     = (const float*)d_in[10];
    const float* w2     = (const float*)d_in[11];
    const float* w3     = (const float*)d_in[12];
    float* out = (float*)d_out;

    float *x1;
    __half *hh, *qkvh, *oh, *ah, *bh, *wq, *wp, *tw1, *tw2, *tw3;
    cudaGetSymbolAddress((void**)&x1,   g_x1);
    cudaGetSymbolAddress((void**)&hh,   g_hh);
    cudaGetSymbolAddress((void**)&qkvh, g_qkvh);
    cudaGetSymbolAddress((void**)&oh,   g_oh);
    cudaGetSymbolAddress((void**)&ah,   g_ah);
    cudaGetSymbolAddress((void**)&bh,   g_bh);
    cudaGetSymbolAddress((void**)&wq,   g_wqh);
    cudaGetSymbolAddress((void**)&wp,   g_wph);
    cudaGetSymbolAddress((void**)&tw1,  g_w1h);
    cudaGetSymbolAddress((void**)&tw2,  g_w2h);
    cudaGetSymbolAddress((void**)&tw3,  g_w3h);

    cudaFuncSetAttribute(hgemm<true,  false, true,  false>, cudaFuncAttributeMaxDynamicSharedMemorySize, HSMEM_BYTES);
    cudaFuncSetAttribute(hgemm<true,  true,  false, false>, cudaFuncAttributeMaxDynamicSharedMemorySize, HSMEM_BYTES);
    cudaFuncSetAttribute(hgemm<false, false, true,  false>, cudaFuncAttributeMaxDynamicSharedMemorySize, HSMEM_BYTES);
    cudaFuncSetAttribute(hgemm<false, false, true,  true >, cudaFuncAttributeMaxDynamicSharedMemorySize, HSMEM_BYTES);
    cudaFuncSetAttribute(hgemm<false, true,  false, false>, cudaFuncAttributeMaxDynamicSharedMemorySize, HSMEM_BYTES);

    // 0) all weights -> fp16 (single fused launch)
    cvt_all_k<<<CVT_N4 / 256, 256>>>(qkv_w, wq, proj_w, wp, w1, tw1, w2, tw2, w3, tw3);

    // 1) hh = LN1(x)
    layernorm_k<<<M_, 256>>>(x, ln1_g, ln1_b, hh);
    // 2) qkvh = hh @ qkv_w^T + qkv_b  (half out)
    hgemm<true, false, true, false><<<dim3(3*C_/128, M_/128), 256, HSMEM_BYTES>>>(
        hh, wq, qkv_b, nullptr, nullptr, qkvh, M_, 3*C_, C_);
    // 3) oh = causal_attention(qkvh)
    flash16_k<<<dim3(N_/FA_BR, B_*H_), 256>>>(qkvh, oh);
    // 4) x1 = x + oh @ proj_w^T + proj_b  (fp32 out)
    hgemm<true, true, false, false><<<dim3(C_/128, M_/128), 256, HSMEM_BYTES>>>(
        oh, wp, proj_b, x, nullptr, x1, M_, C_, C_);
    // 5) hh = LN2(x1)
    layernorm_k<<<M_, 256>>>(x1, ln2_g, ln2_b, hh);
    // 6) ah = hh @ w1^T  (half out)
    hgemm<false, false, true, false><<<dim3(FF_/128, M_/128), 256, HSMEM_BYTES>>>(
        hh, tw1, nullptr, nullptr, nullptr, ah, M_, FF_, C_);
    // 7) bh = silu(ah) * (hh @ w3^T)   (fused epilogue, half out)
    hgemm<false, false, true, true><<<dim3(FF_/128, M_/128), 256, HSMEM_BYTES>>>(
        hh, tw3, nullptr, nullptr, ah, bh, M_, FF_, C_);
    // 8) out = x1 + bh @ w2^T  (fp32 out)
    hgemm<false, true, false, false><<<dim3(C_/128, M_/128), 256, HSMEM_BYTES>>>(
        bh, tw2, nullptr, x1, nullptr, out, M_, C_, FF_);
}